// round 1
// baseline (speedup 1.0000x reference)
#include <cuda_runtime.h>
#include <cstdint>

// ---------------------------------------------------------------------------
// Swin Transformer block: B=16, H=W=64, C=512, NH=4, hd=128, WS=8, SS=4
// tokens = 65536, windows = 1024, N = 64 tokens/window
// ---------------------------------------------------------------------------

#define TOKENS   65536
#define DIMC     512
#define NWIN     1024
#define NHEADS   4
#define HD       128
#define NTOK     64

// scratch layout (floats)
#define OFF_HW     0L
#define OFF_QKV    33554432L     // 65536*512
#define OFF_AOUT   134217728L    // + 65536*1536
#define OFF_X2     167772160L
#define OFF_H2N    201326592L
#define OFF_MLP1   234881024L
#define SCRATCH_FLOATS 369098752L

__device__ float g_scratch[SCRATCH_FLOATS];

// ---------------- packed f32x2 helpers ----------------
__device__ __forceinline__ unsigned long long splat2(float x) {
    unsigned long long r; unsigned u = __float_as_uint(x);
    asm("mov.b64 %0, {%1, %1};" : "=l"(r) : "r"(u));
    return r;
}
__device__ __forceinline__ void unpack2(unsigned long long v, float& lo, float& hi) {
    unsigned a, b;
    asm("mov.b64 {%0, %1}, %2;" : "=r"(a), "=r"(b) : "l"(v));
    lo = __uint_as_float(a); hi = __uint_as_float(b);
}
__device__ __forceinline__ void fma2(unsigned long long& d, unsigned long long a,
                                     unsigned long long b) {
    asm("fma.rn.f32x2 %0, %1, %2, %0;" : "+l"(d) : "l"(a), "l"(b));
}

// ---------------------------------------------------------------------------
// LayerNorm (+ optional shift & window partition remap of the SOURCE row)
// one block per output token row, 128 threads, 4 channels/thread
// ---------------------------------------------------------------------------
__global__ __launch_bounds__(128) void ln_kernel(
    const float* __restrict__ src, const float* __restrict__ gamma,
    const float* __restrict__ beta, float* __restrict__ dst, int do_shift)
{
    int r = blockIdx.x;
    long srow = r;
    if (do_shift) {
        int wi = r >> 6, n = r & 63;
        int b  = wi >> 6, wrem = wi & 63;
        int wy = wrem >> 3, wx = wrem & 7;
        int iy = n >> 3,   ix = n & 7;
        int h = (wy * 8 + iy + 4) & 63;
        int w = (wx * 8 + ix + 4) & 63;
        srow = ((long)b * 64 + h) * 64 + w;
    }
    int c = threadIdx.x * 4;
    float4 v = *(const float4*)(src + srow * DIMC + c);
    float s  = v.x + v.y + v.z + v.w;
    float ss = v.x * v.x + v.y * v.y + v.z * v.z + v.w * v.w;
#pragma unroll
    for (int o = 16; o; o >>= 1) {
        s  += __shfl_xor_sync(0xffffffffu, s,  o);
        ss += __shfl_xor_sync(0xffffffffu, ss, o);
    }
    __shared__ float red[8];
    int warp = threadIdx.x >> 5, lane = threadIdx.x & 31;
    if (lane == 0) { red[warp] = s; red[warp + 4] = ss; }
    __syncthreads();
    s  = red[0] + red[1] + red[2] + red[3];
    ss = red[4] + red[5] + red[6] + red[7];
    float mean = s * (1.0f / 512.0f);
    float var  = ss * (1.0f / 512.0f) - mean * mean;
    float inv  = rsqrtf(var + 1e-5f);
    float4 g4 = *(const float4*)(gamma + c);
    float4 b4 = *(const float4*)(beta + c);
    float4 o;
    o.x = (v.x - mean) * inv * g4.x + b4.x;
    o.y = (v.y - mean) * inv * g4.y + b4.y;
    o.z = (v.z - mean) * inv * g4.z + b4.z;
    o.w = (v.w - mean) * inv * g4.w + b4.w;
    *(float4*)(dst + (long)r * DIMC + c) = o;
}

// ---------------------------------------------------------------------------
// Tiled SGEMM 128x128x16, 8x8 micro-tile, packed f32x2 FMA
// modes: 0 plain(+bias)  1 proj(+bias, window-reverse+unshift, +residual x)
//        2 gelu(+bias)   3 residual(+bias, +res, same row)
// ---------------------------------------------------------------------------
__global__ __launch_bounds__(256, 2) void gemm_kernel(
    const float* __restrict__ A, const float* __restrict__ B,
    const float* __restrict__ bias, float* __restrict__ C,
    int M, int N, int K, int mode, const float* __restrict__ res)
{
    __shared__ float As[16][128];
    __shared__ float Bs[16][128];

    const int tid = threadIdx.x;
    const int tr = tid >> 4;           // 0..15
    const int tc = tid & 15;           // 0..15
    const long brow = (long)blockIdx.y * 128;
    const int  bcol = blockIdx.x * 128;

    const int aRow = tid >> 2;         // 0..63
    const int aCol = (tid & 3) << 2;   // 0,4,8,12
    const int bRow = tid >> 5;         // 0..7
    const int bCol = (tid & 31) << 2;  // 0..124

    unsigned long long acc[8][4];
#pragma unroll
    for (int i = 0; i < 8; i++)
#pragma unroll
        for (int j = 0; j < 4; j++) acc[i][j] = 0ull;

    const float* Ab = A + brow * K;
    const float* Bb = B + bcol;

    for (int k0 = 0; k0 < K; k0 += 16) {
#pragma unroll
        for (int i = 0; i < 2; i++) {
            int rr = aRow + (i << 6);
            float4 a4 = *(const float4*)(Ab + (long)rr * K + k0 + aCol);
            As[aCol + 0][rr] = a4.x;
            As[aCol + 1][rr] = a4.y;
            As[aCol + 2][rr] = a4.z;
            As[aCol + 3][rr] = a4.w;
        }
#pragma unroll
        for (int i = 0; i < 2; i++) {
            int rr = bRow + (i << 3);
            *(float4*)(&Bs[rr][bCol]) = *(const float4*)(Bb + (long)(k0 + rr) * N + bCol);
        }
        __syncthreads();
#pragma unroll
        for (int kk = 0; kk < 16; kk++) {
            unsigned long long b2[4];
#pragma unroll
            for (int j = 0; j < 4; j++)
                b2[j] = *(const unsigned long long*)(&Bs[kk][tc * 8 + j * 2]);
#pragma unroll
            for (int i = 0; i < 8; i++) {
                unsigned long long a2 = splat2(As[kk][tr * 8 + i]);
#pragma unroll
                for (int j = 0; j < 4; j++) fma2(acc[i][j], a2, b2[j]);
            }
        }
        __syncthreads();
    }

    // --------------- epilogue ---------------
    const int col0 = bcol + tc * 8;
    float bv[8];
#pragma unroll
    for (int j = 0; j < 8; j++) bv[j] = bias[col0 + j];

#pragma unroll
    for (int i = 0; i < 8; i++) {
        long r = brow + tr * 8 + i;
        float vals[8];
#pragma unroll
        for (int j = 0; j < 4; j++) unpack2(acc[i][j], vals[2 * j], vals[2 * j + 1]);
#pragma unroll
        for (int j = 0; j < 8; j++) vals[j] += bv[j];

        long orow = r;
        if (mode == 1) {
            int ri = (int)r;
            int wi = ri >> 6, n = ri & 63;
            int b  = wi >> 6, wrem = wi & 63;
            int wy = wrem >> 3, wx = wrem & 7;
            int iy = n >> 3,   ix = n & 7;
            int h = (wy * 8 + iy + 4) & 63;
            int w = (wx * 8 + ix + 4) & 63;
            orow = ((long)b * 64 + h) * 64 + w;
        }
        if (mode == 2) {
#pragma unroll
            for (int j = 0; j < 8; j++) {
                float z = vals[j];
                vals[j] = 0.5f * z * (1.0f + erff(z * 0.70710678118654752f));
            }
        } else if (mode == 1 || mode == 3) {
            const float* rp = res + orow * (long)N + col0;
#pragma unroll
            for (int j = 0; j < 8; j++) vals[j] += rp[j];
        }
        float* cp = C + orow * (long)N + col0;
        *(float4*)cp       = make_float4(vals[0], vals[1], vals[2], vals[3]);
        *(float4*)(cp + 4) = make_float4(vals[4], vals[5], vals[6], vals[7]);
    }
}

// ---------------------------------------------------------------------------
// Windowed attention: one block per (window, head). 256 threads.
// q,k,v are 64x128 fp32 tiles. softmax with rel-pos bias (single channel).
// ---------------------------------------------------------------------------
#define ATTN_SMEM_FLOATS (64*132 + 128*66 + 64*132 + 64*65 + 240)
#define ATTN_SMEM_BYTES  (ATTN_SMEM_FLOATS * 4)

__global__ __launch_bounds__(256, 1) void attn_kernel(
    const float* __restrict__ qkv, const float* __restrict__ bias_table,
    float* __restrict__ out)
{
    extern __shared__ float sm[];
    float* qs = sm;                      // [64][132]  (q * scale)
    float* kt = qs + 64 * 132;           // [128][66]  (k transposed: kt[d][m])
    float* vs = kt + 128 * 66;           // [64][132]
    float* at = vs + 64 * 132;           // [64][65]
    float* bt = at + 64 * 65;            // 225 bias values

    const int wi   = blockIdx.x >> 2;
    const int head = blockIdx.x & 3;
    const int tid  = threadIdx.x;
    const float SCALE = 0.08838834764831845f;   // 1/sqrt(128)

    const float* base = qkv + (long)wi * 64 * 1536 + head * 128;
    for (int idx = tid; idx < 64 * 32; idx += 256) {
        int row = idx >> 5;
        int c   = (idx & 31) << 2;
        const float* p = base + (long)row * 1536 + c;
        float4 q4 = *(const float4*)(p);
        float4 k4 = *(const float4*)(p + 512);
        float4 v4 = *(const float4*)(p + 1024);
        qs[row * 132 + c + 0] = q4.x * SCALE;
        qs[row * 132 + c + 1] = q4.y * SCALE;
        qs[row * 132 + c + 2] = q4.z * SCALE;
        qs[row * 132 + c + 3] = q4.w * SCALE;
        kt[(c + 0) * 66 + row] = k4.x;
        kt[(c + 1) * 66 + row] = k4.y;
        kt[(c + 2) * 66 + row] = k4.z;
        kt[(c + 3) * 66 + row] = k4.w;
        vs[row * 132 + c + 0] = v4.x;
        vs[row * 132 + c + 1] = v4.y;
        vs[row * 132 + c + 2] = v4.z;
        vs[row * 132 + c + 3] = v4.w;
    }
    if (tid < 225) bt[tid] = bias_table[tid];
    __syncthreads();

    const int r = tid >> 2;        // 0..63 query row
    const int g = tid & 3;         // 0..3  quad lane
    const int ry = r >> 3, rx = r & 7;

    // ---- QK^T : thread owns m in pairs (2g+8j, 2g+8j+1), j=0..7 ----
    unsigned long long acc[8];
#pragma unroll
    for (int j = 0; j < 8; j++) acc[j] = 0ull;
#pragma unroll 4
    for (int d = 0; d < 128; d++) {
        unsigned long long qsp = splat2(qs[r * 132 + d]);
#pragma unroll
        for (int j = 0; j < 8; j++)
            fma2(acc[j], qsp, *(const unsigned long long*)(&kt[d * 66 + 2 * g + 8 * j]));
    }

    float e[16];
    float mx = -1e30f;
#pragma unroll
    for (int j = 0; j < 8; j++) {
        float lo, hi; unpack2(acc[j], lo, hi);
        int bidx = (ry - j + 7) * 15 + (rx - 2 * g + 7);
        lo += bt[bidx];
        hi += bt[bidx - 1];
        e[2 * j]     = lo;
        e[2 * j + 1] = hi;
        mx = fmaxf(mx, fmaxf(lo, hi));
    }
    mx = fmaxf(mx, __shfl_xor_sync(0xffffffffu, mx, 1));
    mx = fmaxf(mx, __shfl_xor_sync(0xffffffffu, mx, 2));
    float s = 0.0f;
#pragma unroll
    for (int i = 0; i < 16; i++) { e[i] = __expf(e[i] - mx); s += e[i]; }
    s += __shfl_xor_sync(0xffffffffu, s, 1);
    s += __shfl_xor_sync(0xffffffffu, s, 2);
    float inv = 1.0f / s;
#pragma unroll
    for (int j = 0; j < 8; j++) {
        at[r * 65 + 2 * g + 8 * j]     = e[2 * j]     * inv;
        at[r * 65 + 2 * g + 8 * j + 1] = e[2 * j + 1] * inv;
    }
    __syncwarp();

    // ---- attn @ V : thread owns d chunks d0 = g*4 + 16*jc, jc=0..7 ----
    unsigned long long o2[16];
#pragma unroll
    for (int j = 0; j < 16; j++) o2[j] = 0ull;
    for (int m = 0; m < 64; m++) {
        unsigned long long a2 = splat2(at[r * 65 + m]);
#pragma unroll
        for (int jc = 0; jc < 8; jc++) {
            ulonglong2 vv = *(const ulonglong2*)(&vs[m * 132 + g * 4 + 16 * jc]);
            fma2(o2[2 * jc],     a2, vv.x);
            fma2(o2[2 * jc + 1], a2, vv.y);
        }
    }
    float* op = out + ((long)(wi * 64 + r)) * DIMC + head * HD;
#pragma unroll
    for (int jc = 0; jc < 8; jc++) {
        float4 f;
        unpack2(o2[2 * jc],     f.x, f.y);
        unpack2(o2[2 * jc + 1], f.z, f.w);
        *(float4*)(op + g * 4 + 16 * jc) = f;
    }
}

// ---------------------------------------------------------------------------
extern "C" void kernel_launch(void* const* d_in, const int* in_sizes, int n_in,
                              void* d_out, int out_size)
{
    const float* x      = (const float*)d_in[0];
    const float* ln1_g  = (const float*)d_in[1];
    const float* ln1_b  = (const float*)d_in[2];
    const float* qkv_w  = (const float*)d_in[3];
    const float* qkv_b  = (const float*)d_in[4];
    const float* proj_w = (const float*)d_in[5];
    const float* proj_b = (const float*)d_in[6];
    const float* btab   = (const float*)d_in[7];
    const float* ln2_g  = (const float*)d_in[8];
    const float* ln2_b  = (const float*)d_in[9];
    const float* mlp_w1 = (const float*)d_in[10];
    const float* mlp_b1 = (const float*)d_in[11];
    const float* mlp_w2 = (const float*)d_in[12];
    const float* mlp_b2 = (const float*)d_in[13];
    float* outp = (float*)d_out;

    float* S = nullptr;
    cudaGetSymbolAddress((void**)&S, g_scratch);
    float* hw   = S + OFF_HW;
    float* qkv  = S + OFF_QKV;
    float* aout = S + OFF_AOUT;
    float* x2   = S + OFF_X2;
    float* h2n  = S + OFF_H2N;
    float* m1   = S + OFF_MLP1;

    cudaFuncSetAttribute(attn_kernel, cudaFuncAttributeMaxDynamicSharedMemorySize,
                         ATTN_SMEM_BYTES);

    // 1) LN1 + cyclic shift + window partition
    ln_kernel<<<TOKENS, 128>>>(x, ln1_g, ln1_b, hw, 1);
    // 2) QKV GEMM
    gemm_kernel<<<dim3(12, 512), 256>>>(hw, qkv_w, qkv_b, qkv,
                                        TOKENS, 1536, 512, 0, nullptr);
    // 3) windowed attention
    attn_kernel<<<NWIN * NHEADS, 256, ATTN_SMEM_BYTES>>>(qkv, btab, aout);
    // 4) proj GEMM + window reverse + unshift + residual(x) -> x2
    gemm_kernel<<<dim3(4, 512), 256>>>(aout, proj_w, proj_b, x2,
                                       TOKENS, 512, 512, 1, x);
    // 5) LN2
    ln_kernel<<<TOKENS, 128>>>(x2, ln2_g, ln2_b, h2n, 0);
    // 6) MLP1 + exact GELU
    gemm_kernel<<<dim3(16, 512), 256>>>(h2n, mlp_w1, mlp_b1, m1,
                                        TOKENS, 2048, 512, 2, nullptr);
    // 7) MLP2 + residual(x2) -> output
    gemm_kernel<<<dim3(4, 512), 256>>>(m1, mlp_w2, mlp_b2, outp,
                                       TOKENS, 512, 2048, 3, x2);
}

// round 6
// speedup vs baseline: 1.3393x; 1.3393x over previous
#include <cuda_runtime.h>
#include <cstdint>
#include <mma.h>

using namespace nvcuda;

// ---------------------------------------------------------------------------
// Swin Transformer block, tf32 wmma GEMMs (B loaded row-major from [K,N] —
// no weight transposes, scratch layout identical to the R1-proven kernel)
// B=16, H=W=64, C=512, NH=4, hd=128, WS=8, SS=4
// ---------------------------------------------------------------------------

#define TOKENS   65536
#define DIMC     512
#define NWIN     1024

// scratch layout (floats) — identical to R1
#define OFF_HW     0L
#define OFF_QKV    33554432L
#define OFF_AOUT   134217728L
#define OFF_X2     167772160L
#define OFF_H2N    201326592L
#define OFF_MLP1   234881024L
#define SCRATCH_FLOATS 369098752L

__device__ float g_scratch[SCRATCH_FLOATS];

// ---------------- helpers ----------------
__device__ __forceinline__ float to_tf32(float x) {
    float r; asm("cvt.rna.tf32.f32 %0, %1;" : "=f"(r) : "f"(x)); return r;
}

// ---------------------------------------------------------------------------
// LayerNorm (+ optional shift & window partition of SOURCE row), tf32 output
// ---------------------------------------------------------------------------
__global__ __launch_bounds__(128) void ln_kernel(
    const float* __restrict__ src, const float* __restrict__ gamma,
    const float* __restrict__ beta, float* __restrict__ dst, int do_shift)
{
    int r = blockIdx.x;
    long srow = r;
    if (do_shift) {
        int wi = r >> 6, n = r & 63;
        int b  = wi >> 6, wrem = wi & 63;
        int wy = wrem >> 3, wx = wrem & 7;
        int iy = n >> 3,   ix = n & 7;
        int h = (wy * 8 + iy + 4) & 63;
        int w = (wx * 8 + ix + 4) & 63;
        srow = ((long)b * 64 + h) * 64 + w;
    }
    int c = threadIdx.x * 4;
    float4 v = *(const float4*)(src + srow * DIMC + c);
    float s  = v.x + v.y + v.z + v.w;
    float ss = v.x * v.x + v.y * v.y + v.z * v.z + v.w * v.w;
#pragma unroll
    for (int o = 16; o; o >>= 1) {
        s  += __shfl_xor_sync(0xffffffffu, s,  o);
        ss += __shfl_xor_sync(0xffffffffu, ss, o);
    }
    __shared__ float red[8];
    int warp = threadIdx.x >> 5, lane = threadIdx.x & 31;
    if (lane == 0) { red[warp] = s; red[warp + 4] = ss; }
    __syncthreads();
    s  = red[0] + red[1] + red[2] + red[3];
    ss = red[4] + red[5] + red[6] + red[7];
    float mean = s * (1.0f / 512.0f);
    float var  = ss * (1.0f / 512.0f) - mean * mean;
    float inv  = rsqrtf(var + 1e-5f);
    float4 g4 = *(const float4*)(gamma + c);
    float4 b4 = *(const float4*)(beta + c);
    float4 o;
    o.x = to_tf32((v.x - mean) * inv * g4.x + b4.x);
    o.y = to_tf32((v.y - mean) * inv * g4.y + b4.y);
    o.z = to_tf32((v.z - mean) * inv * g4.z + b4.z);
    o.w = to_tf32((v.w - mean) * inv * g4.w + b4.w);
    *(float4*)(dst + (long)r * DIMC + c) = o;
}

// ---------------------------------------------------------------------------
// tf32 wmma GEMM: C[M,N] = A[M,K] @ W[K,N]
// CTA tile 128x128, BK=32, 8 warps (4m x 2n), warp tile 32x64
// (2x4 wmma 16x16x8 fragments, both operands row-major).
// Shared: As[128][36] | Bs[32][136]; reused as staging[128][68] for epilogue.
// modes: 0 bias | 1 bias+window-reverse+residual | 2 bias+GELU(tf32) | 3 bias+residual
// ---------------------------------------------------------------------------
#define LDA 36
#define LDB 136
#define LDS 68

__global__ __launch_bounds__(256) void wmma_gemm(
    const float* __restrict__ A, const float* __restrict__ W,
    const float* __restrict__ bias, float* __restrict__ C,
    int K, int N, int mode, const float* __restrict__ res)
{
    __shared__ __align__(16) float sraw[128 * LDA + 32 * LDB];  // 35840 B
    float* As = sraw;                 // [128][36]
    float* Bs = sraw + 128 * LDA;     // [32][136]

    const int tid  = threadIdx.x;
    const int warp = tid >> 5;
    const int wm   = warp & 3;    // 0..3 -> 32-row slab
    const int wn   = warp >> 2;   // 0..1 -> 64-col slab
    const long brow = (long)blockIdx.y * 128;
    const int  bcol = blockIdx.x * 128;
    const int  Cn = K >> 5;

    wmma::fragment<wmma::accumulator, 16, 16, 8, float> cf[2][4];
#pragma unroll
    for (int mt = 0; mt < 2; mt++)
#pragma unroll
        for (int nt = 0; nt < 4; nt++) wmma::fill_fragment(cf[mt][nt], 0.0f);

    float4 aReg[4], bReg[4];
    auto gload = [&](int c) {
        const int k0 = c * 32;
#pragma unroll
        for (int i = 0; i < 4; i++) {
            int idx = tid + (i << 8);
            int ar = idx >> 3, ac = (idx & 7) << 2;       // A: [128 rows][32 k]
            aReg[i] = *(const float4*)(A + (brow + ar) * (long)K + k0 + ac);
            int br = idx >> 5, bc = (idx & 31) << 2;      // B: [32 k][128 n]
            bReg[i] = *(const float4*)(W + (long)(k0 + br) * N + bcol + bc);
        }
    };
    auto sstore = [&]() {
#pragma unroll
        for (int i = 0; i < 4; i++) {
            int idx = tid + (i << 8);
            int ar = idx >> 3, ac = (idx & 7) << 2;
            *(float4*)(As + ar * LDA + ac) = aReg[i];
            int br = idx >> 5, bc = (idx & 31) << 2;
            *(float4*)(Bs + br * LDB + bc) = bReg[i];
        }
    };

    gload(0);
    for (int c = 0; c < Cn; c++) {
        sstore();
        __syncthreads();
        if (c + 1 < Cn) gload(c + 1);

#pragma unroll
        for (int ks = 0; ks < 4; ks++) {
            wmma::fragment<wmma::matrix_a, 16, 16, 8, wmma::precision::tf32,
                           wmma::row_major> af[2];
            wmma::fragment<wmma::matrix_b, 16, 16, 8, wmma::precision::tf32,
                           wmma::row_major> bf[4];
#pragma unroll
            for (int mt = 0; mt < 2; mt++) {
                wmma::load_matrix_sync(af[mt], As + (wm * 32 + mt * 16) * LDA + ks * 8,
                                       LDA);
#pragma unroll
                for (int e = 0; e < af[mt].num_elements; e++)
                    af[mt].x[e] = wmma::__float_to_tf32(af[mt].x[e]);
            }
#pragma unroll
            for (int nt = 0; nt < 4; nt++) {
                wmma::load_matrix_sync(bf[nt], Bs + (ks * 8) * LDB + wn * 64 + nt * 16,
                                       LDB);
#pragma unroll
                for (int e = 0; e < bf[nt].num_elements; e++)
                    bf[nt].x[e] = wmma::__float_to_tf32(bf[nt].x[e]);
            }
#pragma unroll
            for (int mt = 0; mt < 2; mt++)
#pragma unroll
                for (int nt = 0; nt < 4; nt++)
                    wmma::mma_sync(cf[mt][nt], af[mt], bf[nt], cf[mt][nt]);
        }
        __syncthreads();
    }

    // ---------------- epilogue: two 64-column passes via shared staging ----
#pragma unroll 1
    for (int pass = 0; pass < 2; pass++) {
        __syncthreads();
        if (wn == pass) {
#pragma unroll
            for (int mt = 0; mt < 2; mt++)
#pragma unroll
                for (int nt = 0; nt < 4; nt++)
                    wmma::store_matrix_sync(sraw + (wm * 32 + mt * 16) * LDS + nt * 16,
                                            cf[mt][nt], LDS, wmma::mem_row_major);
        }
        __syncthreads();

        const int r  = tid >> 1;
        const int ch = (tid & 1) * 32;
        long rr = brow + r;
        long orow = rr;
        if (mode == 1) {
            int ri = (int)rr;
            int wi = ri >> 6, n = ri & 63;
            int b  = wi >> 6, wrem = wi & 63;
            int wy = wrem >> 3, wx = wrem & 7;
            int iy = n >> 3,   ix = n & 7;
            int h = (wy * 8 + iy + 4) & 63;
            int w = (wx * 8 + ix + 4) & 63;
            orow = ((long)b * 64 + h) * 64 + w;
        }
        float* crow = C + orow * (long)N;
        const float* rrow = (mode == 1 || mode == 3) ? res + orow * (long)N : nullptr;
#pragma unroll
        for (int j = 0; j < 32; j += 4) {
            int col = bcol + pass * 64 + ch + j;
            float4 v = *(const float4*)(sraw + r * LDS + ch + j);
            float4 b4 = *(const float4*)(bias + col);
            v.x += b4.x; v.y += b4.y; v.z += b4.z; v.w += b4.w;
            if (mode == 2) {
                v.x = to_tf32(0.5f * v.x * (1.0f + erff(v.x * 0.70710678118654752f)));
                v.y = to_tf32(0.5f * v.y * (1.0f + erff(v.y * 0.70710678118654752f)));
                v.z = to_tf32(0.5f * v.z * (1.0f + erff(v.z * 0.70710678118654752f)));
                v.w = to_tf32(0.5f * v.w * (1.0f + erff(v.w * 0.70710678118654752f)));
            } else if (rrow) {
                float4 r4 = *(const float4*)(rrow + col);
                v.x += r4.x; v.y += r4.y; v.z += r4.z; v.w += r4.w;
            }
            *(float4*)(crow + col) = v;
        }
    }
}

// ---------------------------------------------------------------------------
// Windowed attention (SIMT fp32 / f32x2), output tf32-rounded
// ---------------------------------------------------------------------------
__device__ __forceinline__ unsigned long long splat2(float x) {
    unsigned long long r; unsigned u = __float_as_uint(x);
    asm("mov.b64 %0, {%1, %1};" : "=l"(r) : "r"(u));
    return r;
}
__device__ __forceinline__ void unpack2(unsigned long long v, float& lo, float& hi) {
    unsigned a, b;
    asm("mov.b64 {%0, %1}, %2;" : "=r"(a), "=r"(b) : "l"(v));
    lo = __uint_as_float(a); hi = __uint_as_float(b);
}
__device__ __forceinline__ void fma2(unsigned long long& d, unsigned long long a,
                                     unsigned long long b) {
    asm("fma.rn.f32x2 %0, %1, %2, %0;" : "+l"(d) : "l"(a), "l"(b));
}

#define ATTN_SMEM_FLOATS (64*132 + 128*66 + 64*132 + 64*65 + 240)
#define ATTN_SMEM_BYTES  (ATTN_SMEM_FLOATS * 4)

__global__ __launch_bounds__(256, 1) void attn_kernel(
    const float* __restrict__ qkv, const float* __restrict__ bias_table,
    float* __restrict__ out)
{
    extern __shared__ float sm[];
    float* qs = sm;
    float* kt = qs + 64 * 132;
    float* vs = kt + 128 * 66;
    float* at = vs + 64 * 132;
    float* bt = at + 64 * 65;

    const int wi   = blockIdx.x >> 2;
    const int head = blockIdx.x & 3;
    const int tid  = threadIdx.x;
    const float SCALE = 0.08838834764831845f;

    const float* base = qkv + (long)wi * 64 * 1536 + head * 128;
    for (int idx = tid; idx < 64 * 32; idx += 256) {
        int row = idx >> 5;
        int c   = (idx & 31) << 2;
        const float* p = base + (long)row * 1536 + c;
        float4 q4 = *(const float4*)(p);
        float4 k4 = *(const float4*)(p + 512);
        float4 v4 = *(const float4*)(p + 1024);
        qs[row * 132 + c + 0] = q4.x * SCALE;
        qs[row * 132 + c + 1] = q4.y * SCALE;
        qs[row * 132 + c + 2] = q4.z * SCALE;
        qs[row * 132 + c + 3] = q4.w * SCALE;
        kt[(c + 0) * 66 + row] = k4.x;
        kt[(c + 1) * 66 + row] = k4.y;
        kt[(c + 2) * 66 + row] = k4.z;
        kt[(c + 3) * 66 + row] = k4.w;
        vs[row * 132 + c + 0] = v4.x;
        vs[row * 132 + c + 1] = v4.y;
        vs[row * 132 + c + 2] = v4.z;
        vs[row * 132 + c + 3] = v4.w;
    }
    if (tid < 225) bt[tid] = bias_table[tid];
    __syncthreads();

    const int r = tid >> 2;
    const int g = tid & 3;
    const int ry = r >> 3, rx = r & 7;

    unsigned long long acc[8];
#pragma unroll
    for (int j = 0; j < 8; j++) acc[j] = 0ull;
#pragma unroll 4
    for (int d = 0; d < 128; d++) {
        unsigned long long qsp = splat2(qs[r * 132 + d]);
#pragma unroll
        for (int j = 0; j < 8; j++)
            fma2(acc[j], qsp, *(const unsigned long long*)(&kt[d * 66 + 2 * g + 8 * j]));
    }

    float e[16];
    float mx = -1e30f;
#pragma unroll
    for (int j = 0; j < 8; j++) {
        float lo, hi; unpack2(acc[j], lo, hi);
        int bidx = (ry - j + 7) * 15 + (rx - 2 * g + 7);
        lo += bt[bidx];
        hi += bt[bidx - 1];
        e[2 * j]     = lo;
        e[2 * j + 1] = hi;
        mx = fmaxf(mx, fmaxf(lo, hi));
    }
    mx = fmaxf(mx, __shfl_xor_sync(0xffffffffu, mx, 1));
    mx = fmaxf(mx, __shfl_xor_sync(0xffffffffu, mx, 2));
    float s = 0.0f;
#pragma unroll
    for (int i = 0; i < 16; i++) { e[i] = __expf(e[i] - mx); s += e[i]; }
    s += __shfl_xor_sync(0xffffffffu, s, 1);
    s += __shfl_xor_sync(0xffffffffu, s, 2);
    float inv = 1.0f / s;
#pragma unroll
    for (int j = 0; j < 8; j++) {
        at[r * 65 + 2 * g + 8 * j]     = e[2 * j]     * inv;
        at[r * 65 + 2 * g + 8 * j + 1] = e[2 * j + 1] * inv;
    }
    __syncwarp();

    unsigned long long o2[16];
#pragma unroll
    for (int j = 0; j < 16; j++) o2[j] = 0ull;
    for (int m = 0; m < 64; m++) {
        unsigned long long a2 = splat2(at[r * 65 + m]);
#pragma unroll
        for (int jc = 0; jc < 8; jc++) {
            ulonglong2 vv = *(const ulonglong2*)(&vs[m * 132 + g * 4 + 16 * jc]);
            fma2(o2[2 * jc],     a2, vv.x);
            fma2(o2[2 * jc + 1], a2, vv.y);
        }
    }
    float* op = out + ((long)(wi * 64 + r)) * DIMC + head * 128;
#pragma unroll
    for (int jc = 0; jc < 8; jc++) {
        float4 f;
        unpack2(o2[2 * jc],     f.x, f.y);
        unpack2(o2[2 * jc + 1], f.z, f.w);
        f.x = to_tf32(f.x); f.y = to_tf32(f.y);
        f.z = to_tf32(f.z); f.w = to_tf32(f.w);
        *(float4*)(op + g * 4 + 16 * jc) = f;
    }
}

// ---------------------------------------------------------------------------
extern "C" void kernel_launch(void* const* d_in, const int* in_sizes, int n_in,
                              void* d_out, int out_size)
{
    const float* x      = (const float*)d_in[0];
    const float* ln1_g  = (const float*)d_in[1];
    const float* ln1_b  = (const float*)d_in[2];
    const float* qkv_w  = (const float*)d_in[3];
    const float* qkv_b  = (const float*)d_in[4];
    const float* proj_w = (const float*)d_in[5];
    const float* proj_b = (const float*)d_in[6];
    const float* btab   = (const float*)d_in[7];
    const float* ln2_g  = (const float*)d_in[8];
    const float* ln2_b  = (const float*)d_in[9];
    const float* mlp_w1 = (const float*)d_in[10];
    const float* mlp_b1 = (const float*)d_in[11];
    const float* mlp_w2 = (const float*)d_in[12];
    const float* mlp_b2 = (const float*)d_in[13];
    float* outp = (float*)d_out;

    float* S = nullptr;
    cudaGetSymbolAddress((void**)&S, g_scratch);
    float* hw   = S + OFF_HW;
    float* qkv  = S + OFF_QKV;
    float* aout = S + OFF_AOUT;
    float* x2   = S + OFF_X2;
    float* h2n  = S + OFF_H2N;
    float* m1   = S + OFF_MLP1;

    cudaFuncSetAttribute(attn_kernel, cudaFuncAttributeMaxDynamicSharedMemorySize,
                         ATTN_SMEM_BYTES);

    // 1) LN1 + cyclic shift + window partition
    ln_kernel<<<TOKENS, 128>>>(x, ln1_g, ln1_b, hw, 1);
    // 2) QKV GEMM
    wmma_gemm<<<dim3(12, 512), 256>>>(hw, qkv_w, qkv_b, qkv, 512, 1536, 0, nullptr);
    // 3) windowed attention
    attn_kernel<<<NWIN * 4, 256, ATTN_SMEM_BYTES>>>(qkv, btab, aout);
    // 4) proj + window reverse + unshift + residual(x) -> x2
    wmma_gemm<<<dim3(4, 512), 256>>>(aout, proj_w, proj_b, x2, 512, 512, 1, x);
    // 5) LN2
    ln_kernel<<<TOKENS, 128>>>(x2, ln2_g, ln2_b, h2n, 0);
    // 6) MLP1 + exact GELU
    wmma_gemm<<<dim3(16, 512), 256>>>(h2n, mlp_w1, mlp_b1, m1, 512, 2048, 2, nullptr);
    // 7) MLP2 + residual(x2) -> output
    wmma_gemm<<<dim3(4, 512), 256>>>(m1, mlp_w2, mlp_b2, outp, 2048, 512, 3, x2);
}

// round 7
// speedup vs baseline: 1.5195x; 1.1345x over previous
#include <cuda_runtime.h>
#include <cstdint>
#include <mma.h>

using namespace nvcuda;

// ---------------------------------------------------------------------------
// Swin Transformer block, tf32 wmma GEMMs + cp.async 3-stage pipeline
// B=16, H=W=64, C=512, NH=4, hd=128, WS=8, SS=4
// ---------------------------------------------------------------------------

#define TOKENS   65536
#define DIMC     512
#define NWIN     1024

// scratch layout (floats)
#define OFF_HW     0L
#define OFF_QKV    33554432L
#define OFF_AOUT   134217728L
#define OFF_X2     167772160L
#define OFF_H2N    201326592L
#define OFF_MLP1   234881024L
#define OFF_WQKV   369098752L      // tf32-rounded weight copies (same [K,N] layout)
#define OFF_WPROJ  369885184L
#define OFF_WM1    370147328L
#define OFF_WM2    371195904L
#define SCRATCH_FLOATS 372244480L

__device__ float g_scratch[SCRATCH_FLOATS];

// ---------------- helpers ----------------
__device__ __forceinline__ float to_tf32(float x) {
    float r; asm("cvt.rna.tf32.f32 %0, %1;" : "=f"(r) : "f"(x)); return r;
}
__device__ __forceinline__ uint32_t smem_u32(const void* p) {
    uint32_t a;
    asm("{ .reg .u64 t; cvta.to.shared.u64 t, %1; cvt.u32.u64 %0, t; }" : "=r"(a) : "l"(p));
    return a;
}
__device__ __forceinline__ void cp_async16(uint32_t dst, const void* src) {
    asm volatile("cp.async.cg.shared.global [%0], [%1], 16;" :: "r"(dst), "l"(src));
}

// ---------------------------------------------------------------------------
// tf32 rounding copy (weights)
// ---------------------------------------------------------------------------
__global__ __launch_bounds__(256) void round_copy(
    const float* __restrict__ src, float* __restrict__ dst, int n4)
{
    int i = blockIdx.x * 256 + threadIdx.x;
    if (i < n4) {
        float4 v = ((const float4*)src)[i];
        v.x = to_tf32(v.x); v.y = to_tf32(v.y);
        v.z = to_tf32(v.z); v.w = to_tf32(v.w);
        ((float4*)dst)[i] = v;
    }
}

// ---------------------------------------------------------------------------
// LayerNorm (+ optional shift & window partition of SOURCE row), tf32 output
// ---------------------------------------------------------------------------
__global__ __launch_bounds__(128) void ln_kernel(
    const float* __restrict__ src, const float* __restrict__ gamma,
    const float* __restrict__ beta, float* __restrict__ dst, int do_shift)
{
    int r = blockIdx.x;
    long srow = r;
    if (do_shift) {
        int wi = r >> 6, n = r & 63;
        int b  = wi >> 6, wrem = wi & 63;
        int wy = wrem >> 3, wx = wrem & 7;
        int iy = n >> 3,   ix = n & 7;
        int h = (wy * 8 + iy + 4) & 63;
        int w = (wx * 8 + ix + 4) & 63;
        srow = ((long)b * 64 + h) * 64 + w;
    }
    int c = threadIdx.x * 4;
    float4 v = *(const float4*)(src + srow * DIMC + c);
    float s  = v.x + v.y + v.z + v.w;
    float ss = v.x * v.x + v.y * v.y + v.z * v.z + v.w * v.w;
#pragma unroll
    for (int o = 16; o; o >>= 1) {
        s  += __shfl_xor_sync(0xffffffffu, s,  o);
        ss += __shfl_xor_sync(0xffffffffu, ss, o);
    }
    __shared__ float red[8];
    int warp = threadIdx.x >> 5, lane = threadIdx.x & 31;
    if (lane == 0) { red[warp] = s; red[warp + 4] = ss; }
    __syncthreads();
    s  = red[0] + red[1] + red[2] + red[3];
    ss = red[4] + red[5] + red[6] + red[7];
    float mean = s * (1.0f / 512.0f);
    float var  = ss * (1.0f / 512.0f) - mean * mean;
    float inv  = rsqrtf(var + 1e-5f);
    float4 g4 = *(const float4*)(gamma + c);
    float4 b4 = *(const float4*)(beta + c);
    float4 o;
    o.x = to_tf32((v.x - mean) * inv * g4.x + b4.x);
    o.y = to_tf32((v.y - mean) * inv * g4.y + b4.y);
    o.z = to_tf32((v.z - mean) * inv * g4.z + b4.z);
    o.w = to_tf32((v.w - mean) * inv * g4.w + b4.w);
    *(float4*)(dst + (long)r * DIMC + c) = o;
}

// ---------------------------------------------------------------------------
// tf32 wmma GEMM: C[M,N] = A[M,K] @ W[K,N]   (A, W already tf32-rounded)
// CTA tile 128x128, BK=32, 3-stage cp.async pipeline, 8 warps (4m x 2n),
// warp tile 32x64 (2x4 wmma 16x16x8 fragments, both row-major, no cvt).
// Stage: As[128][36] | Bs[32][136]. Epilogue reuses stage 0 as staging[128][68].
// modes: 0 bias | 1 bias+window-reverse+residual | 2 bias+GELU(tf32) | 3 bias+residual
// ---------------------------------------------------------------------------
#define LDA 36
#define LDB 136
#define STAGE_FLOATS (128 * LDA + 32 * LDB)            // 8960 floats
#define NSTAGE 3
#define GSMEM_BYTES (NSTAGE * STAGE_FLOATS * 4)        // 107520 B
#define LDS 68

__global__ __launch_bounds__(256, 2) void wmma_gemm(
    const float* __restrict__ A, const float* __restrict__ W,
    const float* __restrict__ bias, float* __restrict__ C,
    int K, int N, int mode, const float* __restrict__ res)
{
    extern __shared__ __align__(16) float sraw[];
    const uint32_t sb = smem_u32(sraw);

    const int tid  = threadIdx.x;
    const int warp = tid >> 5;
    const int wm   = warp & 3;    // 0..3 -> 32-row slab
    const int wn   = warp >> 2;   // 0..1 -> 64-col slab
    const long brow = (long)blockIdx.y * 128;
    const int  bcol = blockIdx.x * 128;
    const int  Cn = K >> 5;

    // per-thread load geometry (4 x 16B each for A and B per chunk)
    const int ar = tid >> 3, ac = (tid & 7) << 2;     // A: row 0..31 (+32i), col 0..28
    const int br = tid >> 5, bc = (tid & 31) << 2;    // B: row 0..7 (+8i), col 0..124

    auto issue_load = [&](int c, int s) {
        const int k0 = c * 32;
        const uint32_t as = sb + (uint32_t)(s * STAGE_FLOATS) * 4;
        const uint32_t bs = as + 128 * LDA * 4;
#pragma unroll
        for (int i = 0; i < 4; i++) {
            int r = ar + i * 32;
            cp_async16(as + (r * LDA + ac) * 4, A + (brow + r) * (long)K + k0 + ac);
        }
#pragma unroll
        for (int i = 0; i < 4; i++) {
            int r = br + i * 8;
            cp_async16(bs + (r * LDB + bc) * 4, W + (long)(k0 + r) * N + bcol + bc);
        }
        asm volatile("cp.async.commit_group;" ::: "memory");
    };

    wmma::fragment<wmma::accumulator, 16, 16, 8, float> cf[2][4];
#pragma unroll
    for (int mt = 0; mt < 2; mt++)
#pragma unroll
        for (int nt = 0; nt < 4; nt++) wmma::fill_fragment(cf[mt][nt], 0.0f);

    // prologue: stages 0..NSTAGE-2
    issue_load(0, 0);
    issue_load(1, 1);

    for (int c = 0; c < Cn; c++) {
        asm volatile("cp.async.wait_group 1;" ::: "memory");
        __syncthreads();
        if (c + NSTAGE - 1 < Cn) issue_load(c + NSTAGE - 1, (c + NSTAGE - 1) % NSTAGE);
        else asm volatile("cp.async.commit_group;" ::: "memory");

        const float* As = sraw + (c % NSTAGE) * STAGE_FLOATS;
        const float* Bs = As + 128 * LDA;
#pragma unroll
        for (int ks = 0; ks < 4; ks++) {
            wmma::fragment<wmma::matrix_a, 16, 16, 8, wmma::precision::tf32,
                           wmma::row_major> af[2];
            wmma::fragment<wmma::matrix_b, 16, 16, 8, wmma::precision::tf32,
                           wmma::row_major> bf[4];
#pragma unroll
            for (int mt = 0; mt < 2; mt++)
                wmma::load_matrix_sync(af[mt], As + (wm * 32 + mt * 16) * LDA + ks * 8,
                                       LDA);
#pragma unroll
            for (int nt = 0; nt < 4; nt++)
                wmma::load_matrix_sync(bf[nt], Bs + (ks * 8) * LDB + wn * 64 + nt * 16,
                                       LDB);
#pragma unroll
            for (int mt = 0; mt < 2; mt++)
#pragma unroll
                for (int nt = 0; nt < 4; nt++)
                    wmma::mma_sync(cf[mt][nt], af[mt], bf[nt], cf[mt][nt]);
        }
    }
    asm volatile("cp.async.wait_group 0;" ::: "memory");

    // ---------------- epilogue: two 64-column passes via shared staging ----
#pragma unroll 1
    for (int pass = 0; pass < 2; pass++) {
        __syncthreads();
        if (wn == pass) {
#pragma unroll
            for (int mt = 0; mt < 2; mt++)
#pragma unroll
                for (int nt = 0; nt < 4; nt++)
                    wmma::store_matrix_sync(sraw + (wm * 32 + mt * 16) * LDS + nt * 16,
                                            cf[mt][nt], LDS, wmma::mem_row_major);
        }
        __syncthreads();

        const int r  = tid >> 1;
        const int ch = (tid & 1) * 32;
        long rr = brow + r;
        long orow = rr;
        if (mode == 1) {
            int ri = (int)rr;
            int wi = ri >> 6, n = ri & 63;
            int b  = wi >> 6, wrem = wi & 63;
            int wy = wrem >> 3, wx = wrem & 7;
            int iy = n >> 3,   ix = n & 7;
            int h = (wy * 8 + iy + 4) & 63;
            int w = (wx * 8 + ix + 4) & 63;
            orow = ((long)b * 64 + h) * 64 + w;
        }
        float* crow = C + orow * (long)N;
        const float* rrow = (mode == 1 || mode == 3) ? res + orow * (long)N : nullptr;
#pragma unroll
        for (int j = 0; j < 32; j += 4) {
            int col = bcol + pass * 64 + ch + j;
            float4 v = *(const float4*)(sraw + r * LDS + ch + j);
            float4 b4 = *(const float4*)(bias + col);
            v.x += b4.x; v.y += b4.y; v.z += b4.z; v.w += b4.w;
            if (mode == 2) {
                v.x = to_tf32(0.5f * v.x * (1.0f + erff(v.x * 0.70710678118654752f)));
                v.y = to_tf32(0.5f * v.y * (1.0f + erff(v.y * 0.70710678118654752f)));
                v.z = to_tf32(0.5f * v.z * (1.0f + erff(v.z * 0.70710678118654752f)));
                v.w = to_tf32(0.5f * v.w * (1.0f + erff(v.w * 0.70710678118654752f)));
            } else if (rrow) {
                float4 r4 = *(const float4*)(rrow + col);
                v.x += r4.x; v.y += r4.y; v.z += r4.z; v.w += r4.w;
            }
            *(float4*)(crow + col) = v;
        }
    }
}

// ---------------------------------------------------------------------------
// Windowed attention (SIMT fp32 / f32x2), output tf32-rounded
// ---------------------------------------------------------------------------
__device__ __forceinline__ unsigned long long splat2(float x) {
    unsigned long long r; unsigned u = __float_as_uint(x);
    asm("mov.b64 %0, {%1, %1};" : "=l"(r) : "r"(u));
    return r;
}
__device__ __forceinline__ void unpack2(unsigned long long v, float& lo, float& hi) {
    unsigned a, b;
    asm("mov.b64 {%0, %1}, %2;" : "=r"(a), "=r"(b) : "l"(v));
    lo = __uint_as_float(a); hi = __uint_as_float(b);
}
__device__ __forceinline__ void fma2(unsigned long long& d, unsigned long long a,
                                     unsigned long long b) {
    asm("fma.rn.f32x2 %0, %1, %2, %0;" : "+l"(d) : "l"(a), "l"(b));
}

#define ATTN_SMEM_FLOATS (64*132 + 128*66 + 64*132 + 64*65 + 240)
#define ATTN_SMEM_BYTES  (ATTN_SMEM_FLOATS * 4)

__global__ __launch_bounds__(256, 1) void attn_kernel(
    const float* __restrict__ qkv, const float* __restrict__ bias_table,
    float* __restrict__ out)
{
    extern __shared__ float sm[];
    float* qs = sm;
    float* kt = qs + 64 * 132;
    float* vs = kt + 128 * 66;
    float* at = vs + 64 * 132;
    float* bt = at + 64 * 65;

    const int wi   = blockIdx.x >> 2;
    const int head = blockIdx.x & 3;
    const int tid  = threadIdx.x;
    const float SCALE = 0.08838834764831845f;

    const float* base = qkv + (long)wi * 64 * 1536 + head * 128;
    for (int idx = tid; idx < 64 * 32; idx += 256) {
        int row = idx >> 5;
        int c   = (idx & 31) << 2;
        const float* p = base + (long)row * 1536 + c;
        float4 q4 = *(const float4*)(p);
        float4 k4 = *(const float4*)(p + 512);
        float4 v4 = *(const float4*)(p + 1024);
        qs[row * 132 + c + 0] = q4.x * SCALE;
        qs[row * 132 + c + 1] = q4.y * SCALE;
        qs[row * 132 + c + 2] = q4.z * SCALE;
        qs[row * 132 + c + 3] = q4.w * SCALE;
        kt[(c + 0) * 66 + row] = k4.x;
        kt[(c + 1) * 66 + row] = k4.y;
        kt[(c + 2) * 66 + row] = k4.z;
        kt[(c + 3) * 66 + row] = k4.w;
        vs[row * 132 + c + 0] = v4.x;
        vs[row * 132 + c + 1] = v4.y;
        vs[row * 132 + c + 2] = v4.z;
        vs[row * 132 + c + 3] = v4.w;
    }
    if (tid < 225) bt[tid] = bias_table[tid];
    __syncthreads();

    const int r = tid >> 2;
    const int g = tid & 3;
    const int ry = r >> 3, rx = r & 7;

    unsigned long long acc[8];
#pragma unroll
    for (int j = 0; j < 8; j++) acc[j] = 0ull;
#pragma unroll 4
    for (int d = 0; d < 128; d++) {
        unsigned long long qsp = splat2(qs[r * 132 + d]);
#pragma unroll
        for (int j = 0; j < 8; j++)
            fma2(acc[j], qsp, *(const unsigned long long*)(&kt[d * 66 + 2 * g + 8 * j]));
    }

    float e[16];
    float mx = -1e30f;
#pragma unroll
    for (int j = 0; j < 8; j++) {
        float lo, hi; unpack2(acc[j], lo, hi);
        int bidx = (ry - j + 7) * 15 + (rx - 2 * g + 7);
        lo += bt[bidx];
        hi += bt[bidx - 1];
        e[2 * j]     = lo;
        e[2 * j + 1] = hi;
        mx = fmaxf(mx, fmaxf(lo, hi));
    }
    mx = fmaxf(mx, __shfl_xor_sync(0xffffffffu, mx, 1));
    mx = fmaxf(mx, __shfl_xor_sync(0xffffffffu, mx, 2));
    float s = 0.0f;
#pragma unroll
    for (int i = 0; i < 16; i++) { e[i] = __expf(e[i] - mx); s += e[i]; }
    s += __shfl_xor_sync(0xffffffffu, s, 1);
    s += __shfl_xor_sync(0xffffffffu, s, 2);
    float inv = 1.0f / s;
#pragma unroll
    for (int j = 0; j < 8; j++) {
        at[r * 65 + 2 * g + 8 * j]     = e[2 * j]     * inv;
        at[r * 65 + 2 * g + 8 * j + 1] = e[2 * j + 1] * inv;
    }
    __syncwarp();

    unsigned long long o2[16];
#pragma unroll
    for (int j = 0; j < 16; j++) o2[j] = 0ull;
    for (int m = 0; m < 64; m++) {
        unsigned long long a2 = splat2(at[r * 65 + m]);
#pragma unroll
        for (int jc = 0; jc < 8; jc++) {
            ulonglong2 vv = *(const ulonglong2*)(&vs[m * 132 + g * 4 + 16 * jc]);
            fma2(o2[2 * jc],     a2, vv.x);
            fma2(o2[2 * jc + 1], a2, vv.y);
        }
    }
    float* op = out + ((long)(wi * 64 + r)) * DIMC + head * 128;
#pragma unroll
    for (int jc = 0; jc < 8; jc++) {
        float4 f;
        unpack2(o2[2 * jc],     f.x, f.y);
        unpack2(o2[2 * jc + 1], f.z, f.w);
        f.x = to_tf32(f.x); f.y = to_tf32(f.y);
        f.z = to_tf32(f.z); f.w = to_tf32(f.w);
        *(float4*)(op + g * 4 + 16 * jc) = f;
    }
}

// ---------------------------------------------------------------------------
extern "C" void kernel_launch(void* const* d_in, const int* in_sizes, int n_in,
                              void* d_out, int out_size)
{
    const float* x      = (const float*)d_in[0];
    const float* ln1_g  = (const float*)d_in[1];
    const float* ln1_b  = (const float*)d_in[2];
    const float* qkv_w  = (const float*)d_in[3];
    const float* qkv_b  = (const float*)d_in[4];
    const float* proj_w = (const float*)d_in[5];
    const float* proj_b = (const float*)d_in[6];
    const float* btab   = (const float*)d_in[7];
    const float* ln2_g  = (const float*)d_in[8];
    const float* ln2_b  = (const float*)d_in[9];
    const float* mlp_w1 = (const float*)d_in[10];
    const float* mlp_b1 = (const float*)d_in[11];
    const float* mlp_w2 = (const float*)d_in[12];
    const float* mlp_b2 = (const float*)d_in[13];
    float* outp = (float*)d_out;

    float* S = nullptr;
    cudaGetSymbolAddress((void**)&S, g_scratch);
    float* hw    = S + OFF_HW;
    float* qkv   = S + OFF_QKV;
    float* aout  = S + OFF_AOUT;
    float* x2    = S + OFF_X2;
    float* h2n   = S + OFF_H2N;
    float* m1    = S + OFF_MLP1;
    float* wq    = S + OFF_WQKV;
    float* wp    = S + OFF_WPROJ;
    float* w1    = S + OFF_WM1;
    float* w2    = S + OFF_WM2;

    cudaFuncSetAttribute(attn_kernel, cudaFuncAttributeMaxDynamicSharedMemorySize,
                         ATTN_SMEM_BYTES);
    cudaFuncSetAttribute(wmma_gemm, cudaFuncAttributeMaxDynamicSharedMemorySize,
                         GSMEM_BYTES);

    // tf32-rounded weight copies
    round_copy<<<768, 256>>>(qkv_w, wq, 196608);
    round_copy<<<256, 256>>>(proj_w, wp, 65536);
    round_copy<<<1024, 256>>>(mlp_w1, w1, 262144);
    round_copy<<<1024, 256>>>(mlp_w2, w2, 262144);

    // 1) LN1 + cyclic shift + window partition
    ln_kernel<<<TOKENS, 128>>>(x, ln1_g, ln1_b, hw, 1);
    // 2) QKV GEMM
    wmma_gemm<<<dim3(12, 512), 256, GSMEM_BYTES>>>(hw, wq, qkv_b, qkv,
                                                   512, 1536, 0, nullptr);
    // 3) windowed attention
    attn_kernel<<<NWIN * 4, 256, ATTN_SMEM_BYTES>>>(qkv, btab, aout);
    // 4) proj + window reverse + unshift + residual(x) -> x2
    wmma_gemm<<<dim3(4, 512), 256, GSMEM_BYTES>>>(aout, wp, proj_b, x2,
                                                  512, 512, 1, x);
    // 5) LN2
    ln_kernel<<<TOKENS, 128>>>(x2, ln2_g, ln2_b, h2n, 0);
    // 6) MLP1 + exact GELU
    wmma_gemm<<<dim3(16, 512), 256, GSMEM_BYTES>>>(h2n, w1, mlp_b1, m1,
                                                   512, 2048, 2, nullptr);
    // 7) MLP2 + residual(x2) -> output
    wmma_gemm<<<dim3(4, 512), 256, GSMEM_BYTES>>>(m1, w2, mlp_b2, outp,
                                                  2048, 512, 3, x2);
}

// round 8
// speedup vs baseline: 1.6005x; 1.0533x over previous
#include <cuda_runtime.h>
#include <cstdint>
#include <mma.h>

using namespace nvcuda;

// ---------------------------------------------------------------------------
// Swin Transformer block, tf32 wmma GEMMs, 256x128 CTA tile, cp.async 3-stage
// B=16, H=W=64, C=512, NH=4, hd=128, WS=8, SS=4
// ---------------------------------------------------------------------------

#define TOKENS   65536
#define DIMC     512
#define NWIN     1024

// scratch layout (floats)
#define OFF_HW     0L
#define OFF_QKV    33554432L
#define OFF_AOUT   134217728L
#define OFF_X2     167772160L
#define OFF_H2N    201326592L
#define OFF_MLP1   234881024L
#define OFF_WQKV   369098752L      // tf32-rounded weight copies (same [K,N] layout)
#define OFF_WPROJ  369885184L
#define OFF_WM1    370147328L
#define OFF_WM2    371195904L
#define SCRATCH_FLOATS 372244480L

__device__ float g_scratch[SCRATCH_FLOATS];

// ---------------- helpers ----------------
__device__ __forceinline__ float to_tf32(float x) {
    float r; asm("cvt.rna.tf32.f32 %0, %1;" : "=f"(r) : "f"(x)); return r;
}
__device__ __forceinline__ uint32_t smem_u32(const void* p) {
    uint32_t a;
    asm("{ .reg .u64 t; cvta.to.shared.u64 t, %1; cvt.u32.u64 %0, t; }" : "=r"(a) : "l"(p));
    return a;
}
__device__ __forceinline__ void cp_async16(uint32_t dst, const void* src) {
    asm volatile("cp.async.cg.shared.global [%0], [%1], 16;" :: "r"(dst), "l"(src));
}

// ---------------------------------------------------------------------------
// tf32 rounding copy (weights)
// ---------------------------------------------------------------------------
__global__ __launch_bounds__(256) void round_copy(
    const float* __restrict__ src, float* __restrict__ dst, int n4)
{
    int i = blockIdx.x * 256 + threadIdx.x;
    if (i < n4) {
        float4 v = ((const float4*)src)[i];
        v.x = to_tf32(v.x); v.y = to_tf32(v.y);
        v.z = to_tf32(v.z); v.w = to_tf32(v.w);
        ((float4*)dst)[i] = v;
    }
}

// ---------------------------------------------------------------------------
// LayerNorm (+ optional shift & window partition of SOURCE row), tf32 output
// ---------------------------------------------------------------------------
__global__ __launch_bounds__(128) void ln_kernel(
    const float* __restrict__ src, const float* __restrict__ gamma,
    const float* __restrict__ beta, float* __restrict__ dst, int do_shift)
{
    int r = blockIdx.x;
    long srow = r;
    if (do_shift) {
        int wi = r >> 6, n = r & 63;
        int b  = wi >> 6, wrem = wi & 63;
        int wy = wrem >> 3, wx = wrem & 7;
        int iy = n >> 3,   ix = n & 7;
        int h = (wy * 8 + iy + 4) & 63;
        int w = (wx * 8 + ix + 4) & 63;
        srow = ((long)b * 64 + h) * 64 + w;
    }
    int c = threadIdx.x * 4;
    float4 v = *(const float4*)(src + srow * DIMC + c);
    float s  = v.x + v.y + v.z + v.w;
    float ss = v.x * v.x + v.y * v.y + v.z * v.z + v.w * v.w;
#pragma unroll
    for (int o = 16; o; o >>= 1) {
        s  += __shfl_xor_sync(0xffffffffu, s,  o);
        ss += __shfl_xor_sync(0xffffffffu, ss, o);
    }
    __shared__ float red[8];
    int warp = threadIdx.x >> 5, lane = threadIdx.x & 31;
    if (lane == 0) { red[warp] = s; red[warp + 4] = ss; }
    __syncthreads();
    s  = red[0] + red[1] + red[2] + red[3];
    ss = red[4] + red[5] + red[6] + red[7];
    float mean = s * (1.0f / 512.0f);
    float var  = ss * (1.0f / 512.0f) - mean * mean;
    float inv  = rsqrtf(var + 1e-5f);
    float4 g4 = *(const float4*)(gamma + c);
    float4 b4 = *(const float4*)(beta + c);
    float4 o;
    o.x = to_tf32((v.x - mean) * inv * g4.x + b4.x);
    o.y = to_tf32((v.y - mean) * inv * g4.y + b4.y);
    o.z = to_tf32((v.z - mean) * inv * g4.z + b4.z);
    o.w = to_tf32((v.w - mean) * inv * g4.w + b4.w);
    *(float4*)(dst + (long)r * DIMC + c) = o;
}

// ---------------------------------------------------------------------------
// tf32 wmma GEMM: C[M,N] = A[M,K] @ W[K,N]   (A, W already tf32-rounded)
// CTA tile 256x128, BK=32, 3-stage cp.async, 8 warps (4m x 2n),
// warp tile 64x64 (4x4 wmma 16x16x8 fragments, both row-major).
// Stage: As[256][36] | Bs[32][132] (LDB=132 -> conflict-free fragment rows).
// Epilogue reuses smem as staging[256][68], two 64-col passes.
// modes: 0 bias | 1 bias+window-reverse+residual | 2 bias+GELU(tf32) | 3 bias+residual
// ---------------------------------------------------------------------------
#define LDA 36
#define LDB 132
#define STAGE_FLOATS (256 * LDA + 32 * LDB)            // 13440 floats
#define NSTAGE 3
#define GSMEM_BYTES (NSTAGE * STAGE_FLOATS * 4)        // 161280 B
#define LDS 68

__global__ __launch_bounds__(256, 1) void wmma_gemm(
    const float* __restrict__ A, const float* __restrict__ W,
    const float* __restrict__ bias, float* __restrict__ C,
    int K, int N, int mode, const float* __restrict__ res)
{
    extern __shared__ __align__(16) float sraw[];
    const uint32_t sb = smem_u32(sraw);

    const int tid  = threadIdx.x;
    const int warp = tid >> 5;
    const int wm   = warp & 3;    // 0..3 -> 64-row slab
    const int wn   = warp >> 2;   // 0..1 -> 64-col slab
    const long brow = (long)blockIdx.y * 256;
    const int  bcol = blockIdx.x * 128;
    const int  Cn = K >> 5;

    // per-thread load geometry: A 8 x 16B, B 4 x 16B per chunk
    const int ar = tid >> 3, ac = (tid & 7) << 2;     // A: rows 0..31 (+32i), col 0..28
    const int br = tid >> 5, bc = (tid & 31) << 2;    // B: rows 0..7 (+8i), col 0..124

    auto issue_load = [&](int c, int s) {
        const int k0 = c * 32;
        const uint32_t as = sb + (uint32_t)(s * STAGE_FLOATS) * 4;
        const uint32_t bs = as + 256 * LDA * 4;
#pragma unroll
        for (int i = 0; i < 8; i++) {
            int r = ar + i * 32;
            cp_async16(as + (r * LDA + ac) * 4, A + (brow + r) * (long)K + k0 + ac);
        }
#pragma unroll
        for (int i = 0; i < 4; i++) {
            int r = br + i * 8;
            cp_async16(bs + (r * LDB + bc) * 4, W + (long)(k0 + r) * N + bcol + bc);
        }
        asm volatile("cp.async.commit_group;" ::: "memory");
    };

    wmma::fragment<wmma::accumulator, 16, 16, 8, float> cf[4][4];
#pragma unroll
    for (int mt = 0; mt < 4; mt++)
#pragma unroll
        for (int nt = 0; nt < 4; nt++) wmma::fill_fragment(cf[mt][nt], 0.0f);

    issue_load(0, 0);
    issue_load(1, 1);

    for (int c = 0; c < Cn; c++) {
        asm volatile("cp.async.wait_group 1;" ::: "memory");
        __syncthreads();
        if (c + NSTAGE - 1 < Cn) issue_load(c + NSTAGE - 1, (c + NSTAGE - 1) % NSTAGE);
        else asm volatile("cp.async.commit_group;" ::: "memory");

        const float* As = sraw + (c % NSTAGE) * STAGE_FLOATS;
        const float* Bs = As + 256 * LDA;
#pragma unroll
        for (int ks = 0; ks < 4; ks++) {
            wmma::fragment<wmma::matrix_a, 16, 16, 8, wmma::precision::tf32,
                           wmma::row_major> af[4];
            wmma::fragment<wmma::matrix_b, 16, 16, 8, wmma::precision::tf32,
                           wmma::row_major> bf[4];
#pragma unroll
            for (int mt = 0; mt < 4; mt++)
                wmma::load_matrix_sync(af[mt], As + (wm * 64 + mt * 16) * LDA + ks * 8,
                                       LDA);
#pragma unroll
            for (int nt = 0; nt < 4; nt++)
                wmma::load_matrix_sync(bf[nt], Bs + (ks * 8) * LDB + wn * 64 + nt * 16,
                                       LDB);
#pragma unroll
            for (int mt = 0; mt < 4; mt++)
#pragma unroll
                for (int nt = 0; nt < 4; nt++)
                    wmma::mma_sync(cf[mt][nt], af[mt], bf[nt], cf[mt][nt]);
        }
    }
    asm volatile("cp.async.wait_group 0;" ::: "memory");

    // ---------------- epilogue: two 64-column passes via shared staging ----
#pragma unroll 1
    for (int pass = 0; pass < 2; pass++) {
        __syncthreads();
        if (wn == pass) {
#pragma unroll
            for (int mt = 0; mt < 4; mt++)
#pragma unroll
                for (int nt = 0; nt < 4; nt++)
                    wmma::store_matrix_sync(sraw + (wm * 64 + mt * 16) * LDS + nt * 16,
                                            cf[mt][nt], LDS, wmma::mem_row_major);
        }
        __syncthreads();

        const int r = tid;           // 256 rows, one per thread
        long rr = brow + r;
        long orow = rr;
        if (mode == 1) {
            int ri = (int)rr;
            int wi = ri >> 6, n = ri & 63;
            int b  = wi >> 6, wrem = wi & 63;
            int wy = wrem >> 3, wx = wrem & 7;
            int iy = n >> 3,   ix = n & 7;
            int h = (wy * 8 + iy + 4) & 63;
            int w = (wx * 8 + ix + 4) & 63;
            orow = ((long)b * 64 + h) * 64 + w;
        }
        float* crow = C + orow * (long)N;
        const float* rrow = (mode == 1 || mode == 3) ? res + orow * (long)N : nullptr;
#pragma unroll
        for (int j = 0; j < 64; j += 4) {
            int col = bcol + pass * 64 + j;
            float4 v = *(const float4*)(sraw + r * LDS + j);
            float4 b4 = *(const float4*)(bias + col);
            v.x += b4.x; v.y += b4.y; v.z += b4.z; v.w += b4.w;
            if (mode == 2) {
                v.x = to_tf32(0.5f * v.x * (1.0f + erff(v.x * 0.70710678118654752f)));
                v.y = to_tf32(0.5f * v.y * (1.0f + erff(v.y * 0.70710678118654752f)));
                v.z = to_tf32(0.5f * v.z * (1.0f + erff(v.z * 0.70710678118654752f)));
                v.w = to_tf32(0.5f * v.w * (1.0f + erff(v.w * 0.70710678118654752f)));
            } else if (rrow) {
                float4 r4 = *(const float4*)(rrow + col);
                v.x += r4.x; v.y += r4.y; v.z += r4.z; v.w += r4.w;
            }
            *(float4*)(crow + col) = v;
        }
    }
}

// ---------------------------------------------------------------------------
// Windowed attention (SIMT fp32 / f32x2), output tf32-rounded
// ---------------------------------------------------------------------------
__device__ __forceinline__ unsigned long long splat2(float x) {
    unsigned long long r; unsigned u = __float_as_uint(x);
    asm("mov.b64 %0, {%1, %1};" : "=l"(r) : "r"(u));
    return r;
}
__device__ __forceinline__ void unpack2(unsigned long long v, float& lo, float& hi) {
    unsigned a, b;
    asm("mov.b64 {%0, %1}, %2;" : "=r"(a), "=r"(b) : "l"(v));
    lo = __uint_as_float(a); hi = __uint_as_float(b);
}
__device__ __forceinline__ void fma2(unsigned long long& d, unsigned long long a,
                                     unsigned long long b) {
    asm("fma.rn.f32x2 %0, %1, %2, %0;" : "+l"(d) : "l"(a), "l"(b));
}

#define ATTN_SMEM_FLOATS (64*132 + 128*66 + 64*132 + 64*65 + 240)
#define ATTN_SMEM_BYTES  (ATTN_SMEM_FLOATS * 4)

__global__ __launch_bounds__(256, 1) void attn_kernel(
    const float* __restrict__ qkv, const float* __restrict__ bias_table,
    float* __restrict__ out)
{
    extern __shared__ float sm[];
    float* qs = sm;
    float* kt = qs + 64 * 132;
    float* vs = kt + 128 * 66;
    float* at = vs + 64 * 132;
    float* bt = at + 64 * 65;

    const int wi   = blockIdx.x >> 2;
    const int head = blockIdx.x & 3;
    const int tid  = threadIdx.x;
    const float SCALE = 0.08838834764831845f;

    const float* base = qkv + (long)wi * 64 * 1536 + head * 128;
    for (int idx = tid; idx < 64 * 32; idx += 256) {
        int row = idx >> 5;
        int c   = (idx & 31) << 2;
        const float* p = base + (long)row * 1536 + c;
        float4 q4 = *(const float4*)(p);
        float4 k4 = *(const float4*)(p + 512);
        float4 v4 = *(const float4*)(p + 1024);
        qs[row * 132 + c + 0] = q4.x * SCALE;
        qs[row * 132 + c + 1] = q4.y * SCALE;
        qs[row * 132 + c + 2] = q4.z * SCALE;
        qs[row * 132 + c + 3] = q4.w * SCALE;
        kt[(c + 0) * 66 + row] = k4.x;
        kt[(c + 1) * 66 + row] = k4.y;
        kt[(c + 2) * 66 + row] = k4.z;
        kt[(c + 3) * 66 + row] = k4.w;
        vs[row * 132 + c + 0] = v4.x;
        vs[row * 132 + c + 1] = v4.y;
        vs[row * 132 + c + 2] = v4.z;
        vs[row * 132 + c + 3] = v4.w;
    }
    if (tid < 225) bt[tid] = bias_table[tid];
    __syncthreads();

    const int r = tid >> 2;
    const int g = tid & 3;
    const int ry = r >> 3, rx = r & 7;

    unsigned long long acc[8];
#pragma unroll
    for (int j = 0; j < 8; j++) acc[j] = 0ull;
#pragma unroll 4
    for (int d = 0; d < 128; d++) {
        unsigned long long qsp = splat2(qs[r * 132 + d]);
#pragma unroll
        for (int j = 0; j < 8; j++)
            fma2(acc[j], qsp, *(const unsigned long long*)(&kt[d * 66 + 2 * g + 8 * j]));
    }

    float e[16];
    float mx = -1e30f;
#pragma unroll
    for (int j = 0; j < 8; j++) {
        float lo, hi; unpack2(acc[j], lo, hi);
        int bidx = (ry - j + 7) * 15 + (rx - 2 * g + 7);
        lo += bt[bidx];
        hi += bt[bidx - 1];
        e[2 * j]     = lo;
        e[2 * j + 1] = hi;
        mx = fmaxf(mx, fmaxf(lo, hi));
    }
    mx = fmaxf(mx, __shfl_xor_sync(0xffffffffu, mx, 1));
    mx = fmaxf(mx, __shfl_xor_sync(0xffffffffu, mx, 2));
    float s = 0.0f;
#pragma unroll
    for (int i = 0; i < 16; i++) { e[i] = __expf(e[i] - mx); s += e[i]; }
    s += __shfl_xor_sync(0xffffffffu, s, 1);
    s += __shfl_xor_sync(0xffffffffu, s, 2);
    float inv = 1.0f / s;
#pragma unroll
    for (int j = 0; j < 8; j++) {
        at[r * 65 + 2 * g + 8 * j]     = e[2 * j]     * inv;
        at[r * 65 + 2 * g + 8 * j + 1] = e[2 * j + 1] * inv;
    }
    __syncwarp();

    unsigned long long o2[16];
#pragma unroll
    for (int j = 0; j < 16; j++) o2[j] = 0ull;
    for (int m = 0; m < 64; m++) {
        unsigned long long a2 = splat2(at[r * 65 + m]);
#pragma unroll
        for (int jc = 0; jc < 8; jc++) {
            ulonglong2 vv = *(const ulonglong2*)(&vs[m * 132 + g * 4 + 16 * jc]);
            fma2(o2[2 * jc],     a2, vv.x);
            fma2(o2[2 * jc + 1], a2, vv.y);
        }
    }
    float* op = out + ((long)(wi * 64 + r)) * DIMC + head * 128;
#pragma unroll
    for (int jc = 0; jc < 8; jc++) {
        float4 f;
        unpack2(o2[2 * jc],     f.x, f.y);
        unpack2(o2[2 * jc + 1], f.z, f.w);
        f.x = to_tf32(f.x); f.y = to_tf32(f.y);
        f.z = to_tf32(f.z); f.w = to_tf32(f.w);
        *(float4*)(op + g * 4 + 16 * jc) = f;
    }
}

// ---------------------------------------------------------------------------
extern "C" void kernel_launch(void* const* d_in, const int* in_sizes, int n_in,
                              void* d_out, int out_size)
{
    const float* x      = (const float*)d_in[0];
    const float* ln1_g  = (const float*)d_in[1];
    const float* ln1_b  = (const float*)d_in[2];
    const float* qkv_w  = (const float*)d_in[3];
    const float* qkv_b  = (const float*)d_in[4];
    const float* proj_w = (const float*)d_in[5];
    const float* proj_b = (const float*)d_in[6];
    const float* btab   = (const float*)d_in[7];
    const float* ln2_g  = (const float*)d_in[8];
    const float* ln2_b  = (const float*)d_in[9];
    const float* mlp_w1 = (const float*)d_in[10];
    const float* mlp_b1 = (const float*)d_in[11];
    const float* mlp_w2 = (const float*)d_in[12];
    const float* mlp_b2 = (const float*)d_in[13];
    float* outp = (float*)d_out;

    float* S = nullptr;
    cudaGetSymbolAddress((void**)&S, g_scratch);
    float* hw    = S + OFF_HW;
    float* qkv   = S + OFF_QKV;
    float* aout  = S + OFF_AOUT;
    float* x2    = S + OFF_X2;
    float* h2n   = S + OFF_H2N;
    float* m1    = S + OFF_MLP1;
    float* wq    = S + OFF_WQKV;
    float* wp    = S + OFF_WPROJ;
    float* w1    = S + OFF_WM1;
    float* w2    = S + OFF_WM2;

    cudaFuncSetAttribute(attn_kernel, cudaFuncAttributeMaxDynamicSharedMemorySize,
                         ATTN_SMEM_BYTES);
    cudaFuncSetAttribute(wmma_gemm, cudaFuncAttributeMaxDynamicSharedMemorySize,
                         GSMEM_BYTES);

    // tf32-rounded weight copies
    round_copy<<<768, 256>>>(qkv_w, wq, 196608);
    round_copy<<<256, 256>>>(proj_w, wp, 65536);
    round_copy<<<1024, 256>>>(mlp_w1, w1, 262144);
    round_copy<<<1024, 256>>>(mlp_w2, w2, 262144);

    // 1) LN1 + cyclic shift + window partition
    ln_kernel<<<TOKENS, 128>>>(x, ln1_g, ln1_b, hw, 1);
    // 2) QKV GEMM
    wmma_gemm<<<dim3(12, 256), 256, GSMEM_BYTES>>>(hw, wq, qkv_b, qkv,
                                                   512, 1536, 0, nullptr);
    // 3) windowed attention
    attn_kernel<<<NWIN * 4, 256, ATTN_SMEM_BYTES>>>(qkv, btab, aout);
    // 4) proj + window reverse + unshift + residual(x) -> x2
    wmma_gemm<<<dim3(4, 256), 256, GSMEM_BYTES>>>(aout, wp, proj_b, x2,
                                                  512, 512, 1, x);
    // 5) LN2
    ln_kernel<<<TOKENS, 128>>>(x2, ln2_g, ln2_b, h2n, 0);
    // 6) MLP1 + exact GELU
    wmma_gemm<<<dim3(16, 256), 256, GSMEM_BYTES>>>(h2n, w1, mlp_b1, m1,
                                                   512, 2048, 2, nullptr);
    // 7) MLP2 + residual(x2) -> output
    wmma_gemm<<<dim3(4, 256), 256, GSMEM_BYTES>>>(m1, w2, mlp_b2, outp,
                                                  2048, 512, 3, x2);
}

// round 9
// speedup vs baseline: 2.5100x; 1.5682x over previous
#include <cuda_runtime.h>
#include <cstdint>

// ---------------------------------------------------------------------------
// Swin Transformer block, hand mma.sync tf32 GEMMs (ldmatrix fragments),
// 256x128 CTA tile, cp.async 3-stage. B=16, H=W=64, C=512, NH=4, WS=8, SS=4
// ---------------------------------------------------------------------------

#define TOKENS   65536
#define DIMC     512
#define NWIN     1024

// scratch layout (floats)
#define OFF_HW     0L
#define OFF_QKV    33554432L
#define OFF_AOUT   134217728L
#define OFF_X2     167772160L
#define OFF_H2N    201326592L
#define OFF_MLP1   234881024L
#define OFF_WQKV   369098752L      // transposed tf32 weights [N][K]
#define OFF_WPROJ  369885184L
#define OFF_WM1    370147328L
#define OFF_WM2    371195904L
#define SCRATCH_FLOATS 372244480L

__device__ float g_scratch[SCRATCH_FLOATS];

// ---------------- helpers ----------------
__device__ __forceinline__ float to_tf32(float x) {
    float r; asm("cvt.rna.tf32.f32 %0, %1;" : "=f"(r) : "f"(x)); return r;
}
__device__ __forceinline__ uint32_t smem_u32(const void* p) {
    uint32_t a;
    asm("{ .reg .u64 t; cvta.to.shared.u64 t, %1; cvt.u32.u64 %0, t; }" : "=r"(a) : "l"(p));
    return a;
}
__device__ __forceinline__ void cp_async16(uint32_t dst, const void* src) {
    asm volatile("cp.async.cg.shared.global [%0], [%1], 16;" :: "r"(dst), "l"(src));
}
__device__ __forceinline__ void ldsm_x4(uint32_t& r0, uint32_t& r1, uint32_t& r2,
                                        uint32_t& r3, uint32_t addr) {
    asm volatile("ldmatrix.sync.aligned.m8n8.x4.shared.b16 {%0,%1,%2,%3}, [%4];"
                 : "=r"(r0), "=r"(r1), "=r"(r2), "=r"(r3) : "r"(addr));
}
__device__ __forceinline__ void mma_tf32(float* d, const uint32_t* a, const uint32_t* b) {
    asm volatile(
        "mma.sync.aligned.m16n8k8.row.col.f32.tf32.tf32.f32 "
        "{%0,%1,%2,%3}, {%4,%5,%6,%7}, {%8,%9}, {%0,%1,%2,%3};"
        : "+f"(d[0]), "+f"(d[1]), "+f"(d[2]), "+f"(d[3])
        : "r"(a[0]), "r"(a[1]), "r"(a[2]), "r"(a[3]), "r"(b[0]), "r"(b[1]));
}

// ---------------------------------------------------------------------------
// Weight transpose [K,N] -> [N,K], tf32-rounded
// ---------------------------------------------------------------------------
__global__ __launch_bounds__(256) void transpose_kernel(
    const float* __restrict__ W, float* __restrict__ Wt, int K, int N)
{
    __shared__ float t[32][33];
    int n0 = blockIdx.x * 32, k0 = blockIdx.y * 32;
#pragma unroll
    for (int i = threadIdx.y; i < 32; i += 8)
        t[i][threadIdx.x] = W[(long)(k0 + i) * N + n0 + threadIdx.x];
    __syncthreads();
#pragma unroll
    for (int i = threadIdx.y; i < 32; i += 8)
        Wt[(long)(n0 + i) * K + k0 + threadIdx.x] = to_tf32(t[threadIdx.x][i]);
}

// ---------------------------------------------------------------------------
// LayerNorm (+ optional shift & window partition of SOURCE row), tf32 output
// ---------------------------------------------------------------------------
__global__ __launch_bounds__(128) void ln_kernel(
    const float* __restrict__ src, const float* __restrict__ gamma,
    const float* __restrict__ beta, float* __restrict__ dst, int do_shift)
{
    int r = blockIdx.x;
    long srow = r;
    if (do_shift) {
        int wi = r >> 6, n = r & 63;
        int b  = wi >> 6, wrem = wi & 63;
        int wy = wrem >> 3, wx = wrem & 7;
        int iy = n >> 3,   ix = n & 7;
        int h = (wy * 8 + iy + 4) & 63;
        int w = (wx * 8 + ix + 4) & 63;
        srow = ((long)b * 64 + h) * 64 + w;
    }
    int c = threadIdx.x * 4;
    float4 v = *(const float4*)(src + srow * DIMC + c);
    float s  = v.x + v.y + v.z + v.w;
    float ss = v.x * v.x + v.y * v.y + v.z * v.z + v.w * v.w;
#pragma unroll
    for (int o = 16; o; o >>= 1) {
        s  += __shfl_xor_sync(0xffffffffu, s,  o);
        ss += __shfl_xor_sync(0xffffffffu, ss, o);
    }
    __shared__ float red[8];
    int warp = threadIdx.x >> 5, lane = threadIdx.x & 31;
    if (lane == 0) { red[warp] = s; red[warp + 4] = ss; }
    __syncthreads();
    s  = red[0] + red[1] + red[2] + red[3];
    ss = red[4] + red[5] + red[6] + red[7];
    float mean = s * (1.0f / 512.0f);
    float var  = ss * (1.0f / 512.0f) - mean * mean;
    float inv  = rsqrtf(var + 1e-5f);
    float4 g4 = *(const float4*)(gamma + c);
    float4 b4 = *(const float4*)(beta + c);
    float4 o;
    o.x = to_tf32((v.x - mean) * inv * g4.x + b4.x);
    o.y = to_tf32((v.y - mean) * inv * g4.y + b4.y);
    o.z = to_tf32((v.z - mean) * inv * g4.z + b4.z);
    o.w = to_tf32((v.w - mean) * inv * g4.w + b4.w);
    *(float4*)(dst + (long)r * DIMC + c) = o;
}

// ---------------------------------------------------------------------------
// tf32 mma GEMM: C[M,N] = A[M,K] @ Wt[N,K]^T   (A, Wt already tf32-rounded)
// CTA tile 256x128, BK=32, 3-stage cp.async, 8 warps (4m x 2n),
// warp tile 64x64: 4x8 mma m16n8k8, fragments via ldmatrix.x4 (stride 36 =>
// conflict-free). Epilogue: regs -> smem staging[256][68] -> fused writeout.
// modes: 0 bias | 1 bias+window-reverse+residual | 2 bias+GELU(tf32) | 3 bias+residual
// ---------------------------------------------------------------------------
#define LDT 36
#define A_FLOATS (256 * LDT)                       // 9216
#define STAGE_FLOATS (256 * LDT + 128 * LDT)       // 13824
#define NSTAGE 3
#define GSMEM_BYTES (NSTAGE * STAGE_FLOATS * 4)    // 165888
#define LDS 68

__global__ __launch_bounds__(256, 1) void mma_gemm(
    const float* __restrict__ A, const float* __restrict__ Wt,
    const float* __restrict__ bias, float* __restrict__ C,
    int K, int N, int mode, const float* __restrict__ res)
{
    extern __shared__ __align__(16) float sraw[];
    const uint32_t sb = smem_u32(sraw);

    const int tid  = threadIdx.x;
    const int lane = tid & 31;
    const int warp = tid >> 5;
    const int wm   = warp & 3;    // 0..3 -> 64-row slab
    const int wn   = warp >> 2;   // 0..1 -> 64-col slab
    const long brow = (long)blockIdx.y * 256;
    const int  bcol = blockIdx.x * 128;
    const int  Cn = K >> 5;

    // global->smem geometry: 16B per cp, 8 chunks/row-group
    const int ar = tid >> 3, ac = (tid & 7) << 2;

    auto issue_load = [&](int c, int s) {
        const int k0 = c * 32;
        const uint32_t as = sb + (uint32_t)(s * STAGE_FLOATS) * 4;
        const uint32_t bs = as + A_FLOATS * 4;
#pragma unroll
        for (int i = 0; i < 8; i++) {
            int r = ar + i * 32;
            cp_async16(as + (r * LDT + ac) * 4, A + (brow + r) * (long)K + k0 + ac);
        }
#pragma unroll
        for (int i = 0; i < 4; i++) {
            int r = ar + i * 32;
            cp_async16(bs + (r * LDT + ac) * 4, Wt + (long)(bcol + r) * K + k0 + ac);
        }
        asm volatile("cp.async.commit_group;" ::: "memory");
    };

    float acc[4][8][4];
#pragma unroll
    for (int mt = 0; mt < 4; mt++)
#pragma unroll
        for (int nt = 0; nt < 8; nt++)
#pragma unroll
            for (int q = 0; q < 4; q++) acc[mt][nt][q] = 0.0f;

    // ldmatrix per-lane geometry
    const int lrow = (lane & 7) + ((lane >> 3) & 1) * 8;   // 0..15
    const int lcol = (lane >> 4) * 4;                       // 0 or 4

    issue_load(0, 0);
    issue_load(1, 1);

    for (int c = 0; c < Cn; c++) {
        asm volatile("cp.async.wait_group 1;" ::: "memory");
        __syncthreads();
        if (c + NSTAGE - 1 < Cn) issue_load(c + NSTAGE - 1, (c + NSTAGE - 1) % NSTAGE);
        else asm volatile("cp.async.commit_group;" ::: "memory");

        const uint32_t stage = sb + (uint32_t)((c % NSTAGE) * STAGE_FLOATS) * 4;
        const uint32_t a_off = stage + ((wm * 64 + lrow) * LDT + lcol) * 4;
        const uint32_t b_off = stage + A_FLOATS * 4 + ((wn * 64 + lrow) * LDT + lcol) * 4;
#pragma unroll
        for (int ks = 0; ks < 4; ks++) {
            uint32_t af[4][4], bf[8][2];
#pragma unroll
            for (int mt = 0; mt < 4; mt++)
                ldsm_x4(af[mt][0], af[mt][1], af[mt][2], af[mt][3],
                        a_off + (mt * 16 * LDT + ks * 8) * 4);
#pragma unroll
            for (int np = 0; np < 4; np++) {
                uint32_t r0, r1, r2, r3;
                ldsm_x4(r0, r1, r2, r3, b_off + (np * 16 * LDT + ks * 8) * 4);
                bf[2 * np][0] = r0; bf[2 * np][1] = r2;
                bf[2 * np + 1][0] = r1; bf[2 * np + 1][1] = r3;
            }
#pragma unroll
            for (int mt = 0; mt < 4; mt++)
#pragma unroll
                for (int nt = 0; nt < 8; nt++)
                    mma_tf32(acc[mt][nt], af[mt], bf[nt]);
        }
    }
    asm volatile("cp.async.wait_group 0;" ::: "memory");

    // ---------------- epilogue: two 64-column passes via shared staging ----
    const int gr  = lane >> 2;
    const int tg2 = (lane & 3) * 2;
#pragma unroll 1
    for (int pass = 0; pass < 2; pass++) {
        __syncthreads();
        if (wn == pass) {
#pragma unroll
            for (int mt = 0; mt < 4; mt++)
#pragma unroll
                for (int nt = 0; nt < 8; nt++) {
                    float* st = sraw + (wm * 64 + mt * 16 + gr) * LDS + nt * 8 + tg2;
                    *(float2*)st = make_float2(acc[mt][nt][0], acc[mt][nt][1]);
                    *(float2*)(st + 8 * LDS) = make_float2(acc[mt][nt][2], acc[mt][nt][3]);
                }
        }
        __syncthreads();

        const int r = tid;           // 256 rows, one per thread
        long rr = brow + r;
        long orow = rr;
        if (mode == 1) {
            int ri = (int)rr;
            int wi = ri >> 6, n = ri & 63;
            int b  = wi >> 6, wrem = wi & 63;
            int wy = wrem >> 3, wx = wrem & 7;
            int iy = n >> 3,   ix = n & 7;
            int h = (wy * 8 + iy + 4) & 63;
            int w = (wx * 8 + ix + 4) & 63;
            orow = ((long)b * 64 + h) * 64 + w;
        }
        float* crow = C + orow * (long)N;
        const float* rrow = (mode == 1 || mode == 3) ? res + orow * (long)N : nullptr;
#pragma unroll
        for (int j = 0; j < 64; j += 4) {
            int col = bcol + pass * 64 + j;
            float4 v = *(const float4*)(sraw + r * LDS + j);
            float4 b4 = *(const float4*)(bias + col);
            v.x += b4.x; v.y += b4.y; v.z += b4.z; v.w += b4.w;
            if (mode == 2) {
                v.x = to_tf32(0.5f * v.x * (1.0f + erff(v.x * 0.70710678118654752f)));
                v.y = to_tf32(0.5f * v.y * (1.0f + erff(v.y * 0.70710678118654752f)));
                v.z = to_tf32(0.5f * v.z * (1.0f + erff(v.z * 0.70710678118654752f)));
                v.w = to_tf32(0.5f * v.w * (1.0f + erff(v.w * 0.70710678118654752f)));
            } else if (rrow) {
                float4 r4 = *(const float4*)(rrow + col);
                v.x += r4.x; v.y += r4.y; v.z += r4.z; v.w += r4.w;
            }
            *(float4*)(crow + col) = v;
        }
    }
}

// ---------------------------------------------------------------------------
// Windowed attention (SIMT fp32 / f32x2), output tf32-rounded
// ---------------------------------------------------------------------------
__device__ __forceinline__ unsigned long long splat2(float x) {
    unsigned long long r; unsigned u = __float_as_uint(x);
    asm("mov.b64 %0, {%1, %1};" : "=l"(r) : "r"(u));
    return r;
}
__device__ __forceinline__ void unpack2(unsigned long long v, float& lo, float& hi) {
    unsigned a, b;
    asm("mov.b64 {%0, %1}, %2;" : "=r"(a), "=r"(b) : "l"(v));
    lo = __uint_as_float(a); hi = __uint_as_float(b);
}
__device__ __forceinline__ void fma2(unsigned long long& d, unsigned long long a,
                                     unsigned long long b) {
    asm("fma.rn.f32x2 %0, %1, %2, %0;" : "+l"(d) : "l"(a), "l"(b));
}

#define ATTN_SMEM_FLOATS (64*132 + 128*66 + 64*132 + 64*65 + 240)
#define ATTN_SMEM_BYTES  (ATTN_SMEM_FLOATS * 4)

__global__ __launch_bounds__(256, 1) void attn_kernel(
    const float* __restrict__ qkv, const float* __restrict__ bias_table,
    float* __restrict__ out)
{
    extern __shared__ float sm[];
    float* qs = sm;
    float* kt = qs + 64 * 132;
    float* vs = kt + 128 * 66;
    float* at = vs + 64 * 132;
    float* bt = at + 64 * 65;

    const int wi   = blockIdx.x >> 2;
    const int head = blockIdx.x & 3;
    const int tid  = threadIdx.x;
    const float SCALE = 0.08838834764831845f;

    const float* base = qkv + (long)wi * 64 * 1536 + head * 128;
    for (int idx = tid; idx < 64 * 32; idx += 256) {
        int row = idx >> 5;
        int c   = (idx & 31) << 2;
        const float* p = base + (long)row * 1536 + c;
        float4 q4 = *(const float4*)(p);
        float4 k4 = *(const float4*)(p + 512);
        float4 v4 = *(const float4*)(p + 1024);
        qs[row * 132 + c + 0] = q4.x * SCALE;
        qs[row * 132 + c + 1] = q4.y * SCALE;
        qs[row * 132 + c + 2] = q4.z * SCALE;
        qs[row * 132 + c + 3] = q4.w * SCALE;
        kt[(c + 0) * 66 + row] = k4.x;
        kt[(c + 1) * 66 + row] = k4.y;
        kt[(c + 2) * 66 + row] = k4.z;
        kt[(c + 3) * 66 + row] = k4.w;
        vs[row * 132 + c + 0] = v4.x;
        vs[row * 132 + c + 1] = v4.y;
        vs[row * 132 + c + 2] = v4.z;
        vs[row * 132 + c + 3] = v4.w;
    }
    if (tid < 225) bt[tid] = bias_table[tid];
    __syncthreads();

    const int r = tid >> 2;
    const int g = tid & 3;
    const int ry = r >> 3, rx = r & 7;

    unsigned long long acc[8];
#pragma unroll
    for (int j = 0; j < 8; j++) acc[j] = 0ull;
#pragma unroll 4
    for (int d = 0; d < 128; d++) {
        unsigned long long qsp = splat2(qs[r * 132 + d]);
#pragma unroll
        for (int j = 0; j < 8; j++)
            fma2(acc[j], qsp, *(const unsigned long long*)(&kt[d * 66 + 2 * g + 8 * j]));
    }

    float e[16];
    float mx = -1e30f;
#pragma unroll
    for (int j = 0; j < 8; j++) {
        float lo, hi; unpack2(acc[j], lo, hi);
        int bidx = (ry - j + 7) * 15 + (rx - 2 * g + 7);
        lo += bt[bidx];
        hi += bt[bidx - 1];
        e[2 * j]     = lo;
        e[2 * j + 1] = hi;
        mx = fmaxf(mx, fmaxf(lo, hi));
    }
    mx = fmaxf(mx, __shfl_xor_sync(0xffffffffu, mx, 1));
    mx = fmaxf(mx, __shfl_xor_sync(0xffffffffu, mx, 2));
    float s = 0.0f;
#pragma unroll
    for (int i = 0; i < 16; i++) { e[i] = __expf(e[i] - mx); s += e[i]; }
    s += __shfl_xor_sync(0xffffffffu, s, 1);
    s += __shfl_xor_sync(0xffffffffu, s, 2);
    float inv = 1.0f / s;
#pragma unroll
    for (int j = 0; j < 8; j++) {
        at[r * 65 + 2 * g + 8 * j]     = e[2 * j]     * inv;
        at[r * 65 + 2 * g + 8 * j + 1] = e[2 * j + 1] * inv;
    }
    __syncwarp();

    unsigned long long o2[16];
#pragma unroll
    for (int j = 0; j < 16; j++) o2[j] = 0ull;
    for (int m = 0; m < 64; m++) {
        unsigned long long a2 = splat2(at[r * 65 + m]);
#pragma unroll
        for (int jc = 0; jc < 8; jc++) {
            ulonglong2 vv = *(const ulonglong2*)(&vs[m * 132 + g * 4 + 16 * jc]);
            fma2(o2[2 * jc],     a2, vv.x);
            fma2(o2[2 * jc + 1], a2, vv.y);
        }
    }
    float* op = out + ((long)(wi * 64 + r)) * DIMC + head * 128;
#pragma unroll
    for (int jc = 0; jc < 8; jc++) {
        float4 f;
        unpack2(o2[2 * jc],     f.x, f.y);
        unpack2(o2[2 * jc + 1], f.z, f.w);
        f.x = to_tf32(f.x); f.y = to_tf32(f.y);
        f.z = to_tf32(f.z); f.w = to_tf32(f.w);
        *(float4*)(op + g * 4 + 16 * jc) = f;
    }
}

// ---------------------------------------------------------------------------
extern "C" void kernel_launch(void* const* d_in, const int* in_sizes, int n_in,
                              void* d_out, int out_size)
{
    const float* x      = (const float*)d_in[0];
    const float* ln1_g  = (const float*)d_in[1];
    const float* ln1_b  = (const float*)d_in[2];
    const float* qkv_w  = (const float*)d_in[3];
    const float* qkv_b  = (const float*)d_in[4];
    const float* proj_w = (const float*)d_in[5];
    const float* proj_b = (const float*)d_in[6];
    const float* btab   = (const float*)d_in[7];
    const float* ln2_g  = (const float*)d_in[8];
    const float* ln2_b  = (const float*)d_in[9];
    const float* mlp_w1 = (const float*)d_in[10];
    const float* mlp_b1 = (const float*)d_in[11];
    const float* mlp_w2 = (const float*)d_in[12];
    const float* mlp_b2 = (const float*)d_in[13];
    float* outp = (float*)d_out;

    float* S = nullptr;
    cudaGetSymbolAddress((void**)&S, g_scratch);
    float* hw    = S + OFF_HW;
    float* qkv   = S + OFF_QKV;
    float* aout  = S + OFF_AOUT;
    float* x2    = S + OFF_X2;
    float* h2n   = S + OFF_H2N;
    float* m1    = S + OFF_MLP1;
    float* wq    = S + OFF_WQKV;
    float* wp    = S + OFF_WPROJ;
    float* w1    = S + OFF_WM1;
    float* w2    = S + OFF_WM2;

    cudaFuncSetAttribute(attn_kernel, cudaFuncAttributeMaxDynamicSharedMemorySize,
                         ATTN_SMEM_BYTES);
    cudaFuncSetAttribute(mma_gemm, cudaFuncAttributeMaxDynamicSharedMemorySize,
                         GSMEM_BYTES);

    // transposed tf32 weights [N][K]
    transpose_kernel<<<dim3(48, 16), dim3(32, 8)>>>(qkv_w, wq, 512, 1536);
    transpose_kernel<<<dim3(16, 16), dim3(32, 8)>>>(proj_w, wp, 512, 512);
    transpose_kernel<<<dim3(64, 16), dim3(32, 8)>>>(mlp_w1, w1, 512, 2048);
    transpose_kernel<<<dim3(16, 64), dim3(32, 8)>>>(mlp_w2, w2, 2048, 512);

    // 1) LN1 + cyclic shift + window partition
    ln_kernel<<<TOKENS, 128>>>(x, ln1_g, ln1_b, hw, 1);
    // 2) QKV GEMM
    mma_gemm<<<dim3(12, 256), 256, GSMEM_BYTES>>>(hw, wq, qkv_b, qkv,
                                                  512, 1536, 0, nullptr);
    // 3) windowed attention
    attn_kernel<<<NWIN * 4, 256, ATTN_SMEM_BYTES>>>(qkv, btab, aout);
    // 4) proj + window reverse + unshift + residual(x) -> x2
    mma_gemm<<<dim3(4, 256), 256, GSMEM_BYTES>>>(aout, wp, proj_b, x2,
                                                 512, 512, 1, x);
    // 5) LN2
    ln_kernel<<<TOKENS, 128>>>(x2, ln2_g, ln2_b, h2n, 0);
    // 6) MLP1 + exact GELU
    mma_gemm<<<dim3(16, 256), 256, GSMEM_BYTES>>>(h2n, w1, mlp_b1, m1,
                                                  512, 2048, 2, nullptr);
    // 7) MLP2 + residual(x2) -> output
    mma_gemm<<<dim3(4, 256), 256, GSMEM_BYTES>>>(m1, w2, mlp_b2, outp,
                                                 2048, 512, 3, x2);
}

// round 11
// speedup vs baseline: 3.5645x; 1.4201x over previous
#include <cuda_runtime.h>
#include <cuda_bf16.h>
#include <cstdint>

// ---------------------------------------------------------------------------
// Swin Transformer block, bf16 mma.sync m16n8k16 GEMMs (ldmatrix fragments),
// 256x128 CTA tile, cp.async 4-stage. B=16, H=W=64, C=512, NH=4, WS=8, SS=4
// ---------------------------------------------------------------------------

#define TOKENS   65536
#define DIMC     512
#define NWIN     1024

// scratch layout (float-indexed offsets; bf16 regions reinterpret, use <= half)
#define OFF_HW     0L
#define OFF_QKV    33554432L
#define OFF_AOUT   134217728L
#define OFF_X2     167772160L
#define OFF_H2N    201326592L
#define OFF_MLP1   234881024L
#define OFF_WQKV   369098752L      // transposed bf16 weights [N][K]
#define OFF_WPROJ  369885184L
#define OFF_WM1    370147328L
#define OFF_WM2    371195904L
#define SCRATCH_FLOATS 372244480L

__device__ float g_scratch[SCRATCH_FLOATS];

// ---------------- helpers ----------------
__device__ __forceinline__ uint32_t smem_u32(const void* p) {
    uint32_t a;
    asm("{ .reg .u64 t; cvta.to.shared.u64 t, %1; cvt.u32.u64 %0, t; }" : "=r"(a) : "l"(p));
    return a;
}
__device__ __forceinline__ void cp_async16(uint32_t dst, const void* src) {
    asm volatile("cp.async.cg.shared.global [%0], [%1], 16;" :: "r"(dst), "l"(src));
}
__device__ __forceinline__ void ldsm_x4(uint32_t& r0, uint32_t& r1, uint32_t& r2,
                                        uint32_t& r3, uint32_t addr) {
    asm volatile("ldmatrix.sync.aligned.m8n8.x4.shared.b16 {%0,%1,%2,%3}, [%4];"
                 : "=r"(r0), "=r"(r1), "=r"(r2), "=r"(r3) : "r"(addr));
}
__device__ __forceinline__ void mma_bf16(float* d, const uint32_t* a, const uint32_t* b) {
    asm volatile(
        "mma.sync.aligned.m16n8k16.row.col.f32.bf16.bf16.f32 "
        "{%0,%1,%2,%3}, {%4,%5,%6,%7}, {%8,%9}, {%0,%1,%2,%3};"
        : "+f"(d[0]), "+f"(d[1]), "+f"(d[2]), "+f"(d[3])
        : "r"(a[0]), "r"(a[1]), "r"(a[2]), "r"(a[3]), "r"(b[0]), "r"(b[1]));
}
__device__ __forceinline__ uint32_t pack_bf2(float x, float y) {
    __nv_bfloat162 p = __float22bfloat162_rn(make_float2(x, y));
    return *(uint32_t*)&p;
}

// ---------------------------------------------------------------------------
// Weight transpose [K,N] -> [N,K], bf16
// ---------------------------------------------------------------------------
__global__ __launch_bounds__(256) void transpose_kernel(
    const float* __restrict__ W, __nv_bfloat16* __restrict__ Wt, int K, int N)
{
    __shared__ float t[32][33];
    int n0 = blockIdx.x * 32, k0 = blockIdx.y * 32;
#pragma unroll
    for (int i = threadIdx.y; i < 32; i += 8)
        t[i][threadIdx.x] = W[(long)(k0 + i) * N + n0 + threadIdx.x];
    __syncthreads();
#pragma unroll
    for (int i = threadIdx.y; i < 32; i += 8)
        Wt[(long)(n0 + i) * K + k0 + threadIdx.x] = __float2bfloat16_rn(t[threadIdx.x][i]);
}

// ---------------------------------------------------------------------------
// LayerNorm (+ optional shift & window partition of SOURCE row), bf16 output
// ---------------------------------------------------------------------------
__global__ __launch_bounds__(128) void ln_kernel(
    const float* __restrict__ src, const float* __restrict__ gamma,
    const float* __restrict__ beta, __nv_bfloat16* __restrict__ dst, int do_shift)
{
    int r = blockIdx.x;
    long srow = r;
    if (do_shift) {
        int wi = r >> 6, n = r & 63;
        int b  = wi >> 6, wrem = wi & 63;
        int wy = wrem >> 3, wx = wrem & 7;
        int iy = n >> 3,   ix = n & 7;
        int h = (wy * 8 + iy + 4) & 63;
        int w = (wx * 8 + ix + 4) & 63;
        srow = ((long)b * 64 + h) * 64 + w;
    }
    int c = threadIdx.x * 4;
    float4 v = *(const float4*)(src + srow * DIMC + c);
    float s  = v.x + v.y + v.z + v.w;
    float ss = v.x * v.x + v.y * v.y + v.z * v.z + v.w * v.w;
#pragma unroll
    for (int o = 16; o; o >>= 1) {
        s  += __shfl_xor_sync(0xffffffffu, s,  o);
        ss += __shfl_xor_sync(0xffffffffu, ss, o);
    }
    __shared__ float red[8];
    int warp = threadIdx.x >> 5, lane = threadIdx.x & 31;
    if (lane == 0) { red[warp] = s; red[warp + 4] = ss; }
    __syncthreads();
    s  = red[0] + red[1] + red[2] + red[3];
    ss = red[4] + red[5] + red[6] + red[7];
    float mean = s * (1.0f / 512.0f);
    float var  = ss * (1.0f / 512.0f) - mean * mean;
    float inv  = rsqrtf(var + 1e-5f);
    float4 g4 = *(const float4*)(gamma + c);
    float4 b4 = *(const float4*)(beta + c);
    uint2 pk;
    pk.x = pack_bf2((v.x - mean) * inv * g4.x + b4.x, (v.y - mean) * inv * g4.y + b4.y);
    pk.y = pack_bf2((v.z - mean) * inv * g4.z + b4.z, (v.w - mean) * inv * g4.w + b4.w);
    *(uint2*)(dst + (long)r * DIMC + c) = pk;
}

// ---------------------------------------------------------------------------
// bf16 mma GEMM: C[M,N] = A[M,K] @ Wt[N,K]^T   (A, Wt bf16; acc fp32)
// CTA tile 256x128, BK=32 halves, 4-stage cp.async, 8 warps (4m x 2n),
// warp tile 64x64: per chunk 2 x (8 ldsm.x4 + 32 mma m16n8k16).
// smem stride 40 halves (80B) -> conflict-free ldmatrix rows (banks 20r mod 32).
// Loader: A 256r x 32h: ar=tid>>2 (0..63), ac=(tid&3)*8 (0..24), 4 row-iters.
// Epilogue: regs -> smem staging[256][68] (fp32) -> fused writeout.
// modes: 0 bias(f32 out) | 1 bias+winrev+residual(f32) | 2 bias+GELU(bf16 out)
//        | 3 bias+residual(f32)
// ---------------------------------------------------------------------------
#define LDH 40
#define A_HALVES (256 * LDH)                       // 10240
#define STAGE_HALVES (256 * LDH + 128 * LDH)       // 15360 (30720 B)
#define NSTAGE 4
#define GSMEM_BYTES (NSTAGE * STAGE_HALVES * 2)    // 122880
#define LDS 68

__global__ __launch_bounds__(256, 1) void mma_gemm(
    const __nv_bfloat16* __restrict__ A, const __nv_bfloat16* __restrict__ Wt,
    const float* __restrict__ bias, void* __restrict__ Cv,
    int K, int N, int mode, const float* __restrict__ res)
{
    extern __shared__ __align__(16) float sraw[];
    const uint32_t sb = smem_u32(sraw);

    const int tid  = threadIdx.x;
    const int lane = tid & 31;
    const int warp = tid >> 5;
    const int wm   = warp & 3;    // 0..3 -> 64-row slab
    const int wn   = warp >> 2;   // 0..1 -> 64-col slab
    const long brow = (long)blockIdx.y * 256;
    const int  bcol = blockIdx.x * 128;
    const int  Cn = K >> 5;

    // global->smem geometry: 16B (8 halves) per cp; chunk = 32 halves/row
    const int ar = tid >> 2;             // 0..63
    const int ac = (tid & 3) << 3;       // 0,8,16,24 halves

    auto issue_load = [&](int c, int s) {
        const int k0 = c * 32;                       // halves
        const uint32_t as = sb + (uint32_t)(s * STAGE_HALVES) * 2;
        const uint32_t bs = as + A_HALVES * 2;
#pragma unroll
        for (int i = 0; i < 4; i++) {
            int r = ar + i * 64;
            cp_async16(as + (r * LDH + ac) * 2, A + (brow + r) * (long)K + k0 + ac);
        }
#pragma unroll
        for (int i = 0; i < 2; i++) {
            int r = ar + i * 64;
            cp_async16(bs + (r * LDH + ac) * 2, Wt + (long)(bcol + r) * K + k0 + ac);
        }
        asm volatile("cp.async.commit_group;" ::: "memory");
    };

    float acc[4][8][4];
#pragma unroll
    for (int mt = 0; mt < 4; mt++)
#pragma unroll
        for (int nt = 0; nt < 8; nt++)
#pragma unroll
            for (int q = 0; q < 4; q++) acc[mt][nt][q] = 0.0f;

    // ldmatrix per-lane geometry
    const int lrow = (lane & 7) + ((lane >> 3) & 1) * 8;   // 0..15
    const int lcol = (lane >> 4) * 8;                       // halves: 0 or 8

    issue_load(0, 0);
    issue_load(1, 1);
    issue_load(2, 2);

    for (int c = 0; c < Cn; c++) {
        asm volatile("cp.async.wait_group 2;" ::: "memory");
        __syncthreads();
        if (c + NSTAGE - 1 < Cn) issue_load(c + NSTAGE - 1, (c + NSTAGE - 1) % NSTAGE);
        else asm volatile("cp.async.commit_group;" ::: "memory");

        const uint32_t stage = sb + (uint32_t)((c % NSTAGE) * STAGE_HALVES) * 2;
        const uint32_t a_off = stage + ((wm * 64 + lrow) * LDH + lcol) * 2;
        const uint32_t b_off = stage + A_HALVES * 2 + ((wn * 64 + lrow) * LDH + lcol) * 2;
#pragma unroll
        for (int ks = 0; ks < 2; ks++) {
            uint32_t af[4][4], bf[8][2];
#pragma unroll
            for (int mt = 0; mt < 4; mt++)
                ldsm_x4(af[mt][0], af[mt][1], af[mt][2], af[mt][3],
                        a_off + (mt * 16 * LDH + ks * 16) * 2);
#pragma unroll
            for (int np = 0; np < 4; np++) {
                uint32_t r0, r1, r2, r3;
                ldsm_x4(r0, r1, r2, r3, b_off + (np * 16 * LDH + ks * 16) * 2);
                bf[2 * np][0] = r0; bf[2 * np][1] = r2;
                bf[2 * np + 1][0] = r1; bf[2 * np + 1][1] = r3;
            }
#pragma unroll
            for (int mt = 0; mt < 4; mt++)
#pragma unroll
                for (int nt = 0; nt < 8; nt++)
                    mma_bf16(acc[mt][nt], af[mt], bf[nt]);
        }
    }
    asm volatile("cp.async.wait_group 0;" ::: "memory");

    // ---------------- epilogue: two 64-column passes via shared staging ----
    const int gr  = lane >> 2;
    const int tg2 = (lane & 3) * 2;
#pragma unroll 1
    for (int pass = 0; pass < 2; pass++) {
        __syncthreads();
        if (wn == pass) {
#pragma unroll
            for (int mt = 0; mt < 4; mt++)
#pragma unroll
                for (int nt = 0; nt < 8; nt++) {
                    float* st = sraw + (wm * 64 + mt * 16 + gr) * LDS + nt * 8 + tg2;
                    *(float2*)st = make_float2(acc[mt][nt][0], acc[mt][nt][1]);
                    *(float2*)(st + 8 * LDS) = make_float2(acc[mt][nt][2], acc[mt][nt][3]);
                }
        }
        __syncthreads();

        const int r = tid;           // 256 rows, one per thread
        long rr = brow + r;
        long orow = rr;
        if (mode == 1) {
            int ri = (int)rr;
            int wi = ri >> 6, n = ri & 63;
            int b  = wi >> 6, wrem = wi & 63;
            int wy = wrem >> 3, wx = wrem & 7;
            int iy = n >> 3,   ix = n & 7;
            int h = (wy * 8 + iy + 4) & 63;
            int w = (wx * 8 + ix + 4) & 63;
            orow = ((long)b * 64 + h) * 64 + w;
        }
        float* crow = (mode == 2) ? nullptr : (float*)Cv + orow * (long)N;
        __nv_bfloat16* crow_bf = (mode == 2)
            ? (__nv_bfloat16*)Cv + orow * (long)N : nullptr;
        const float* rrow = (mode == 1 || mode == 3) ? res + orow * (long)N : nullptr;
#pragma unroll
        for (int j = 0; j < 64; j += 4) {
            int col = bcol + pass * 64 + j;
            float4 v = *(const float4*)(sraw + r * LDS + j);
            float4 b4 = *(const float4*)(bias + col);
            v.x += b4.x; v.y += b4.y; v.z += b4.z; v.w += b4.w;
            if (mode == 2) {
                v.x = 0.5f * v.x * (1.0f + erff(v.x * 0.70710678118654752f));
                v.y = 0.5f * v.y * (1.0f + erff(v.y * 0.70710678118654752f));
                v.z = 0.5f * v.z * (1.0f + erff(v.z * 0.70710678118654752f));
                v.w = 0.5f * v.w * (1.0f + erff(v.w * 0.70710678118654752f));
                uint2 pk;
                pk.x = pack_bf2(v.x, v.y);
                pk.y = pack_bf2(v.z, v.w);
                *(uint2*)(crow_bf + col) = pk;
            } else {
                if (rrow) {
                    float4 r4 = *(const float4*)(rrow + col);
                    v.x += r4.x; v.y += r4.y; v.z += r4.z; v.w += r4.w;
                }
                *(float4*)(crow + col) = v;
            }
        }
    }
}

// ---------------------------------------------------------------------------
// Windowed attention (SIMT fp32 / f32x2), bf16 output
// ---------------------------------------------------------------------------
__device__ __forceinline__ unsigned long long splat2(float x) {
    unsigned long long r; unsigned u = __float_as_uint(x);
    asm("mov.b64 %0, {%1, %1};" : "=l"(r) : "r"(u));
    return r;
}
__device__ __forceinline__ void unpack2(unsigned long long v, float& lo, float& hi) {
    unsigned a, b;
    asm("mov.b64 {%0, %1}, %2;" : "=r"(a), "=r"(b) : "l"(v));
    lo = __uint_as_float(a); hi = __uint_as_float(b);
}
__device__ __forceinline__ void fma2(unsigned long long& d, unsigned long long a,
                                     unsigned long long b) {
    asm("fma.rn.f32x2 %0, %1, %2, %0;" : "+l"(d) : "l"(a), "l"(b));
}

#define ATTN_SMEM_FLOATS (64*132 + 128*66 + 64*132 + 64*65 + 240)
#define ATTN_SMEM_BYTES  (ATTN_SMEM_FLOATS * 4)

__global__ __launch_bounds__(256, 1) void attn_kernel(
    const float* __restrict__ qkv, const float* __restrict__ bias_table,
    __nv_bfloat16* __restrict__ out)
{
    extern __shared__ float sm[];
    float* qs = sm;
    float* kt = qs + 64 * 132;
    float* vs = kt + 128 * 66;
    float* at = vs + 64 * 132;
    float* bt = at + 64 * 65;

    const int wi   = blockIdx.x >> 2;
    const int head = blockIdx.x & 3;
    const int tid  = threadIdx.x;
    const float SCALE = 0.08838834764831845f;

    const float* base = qkv + (long)wi * 64 * 1536 + head * 128;
    for (int idx = tid; idx < 64 * 32; idx += 256) {
        int row = idx >> 5;
        int c   = (idx & 31) << 2;
        const float* p = base + (long)row * 1536 + c;
        float4 q4 = *(const float4*)(p);
        float4 k4 = *(const float4*)(p + 512);
        float4 v4 = *(const float4*)(p + 1024);
        qs[row * 132 + c + 0] = q4.x * SCALE;
        qs[row * 132 + c + 1] = q4.y * SCALE;
        qs[row * 132 + c + 2] = q4.z * SCALE;
        qs[row * 132 + c + 3] = q4.w * SCALE;
        kt[(c + 0) * 66 + row] = k4.x;
        kt[(c + 1) * 66 + row] = k4.y;
        kt[(c + 2) * 66 + row] = k4.z;
        kt[(c + 3) * 66 + row] = k4.w;
        vs[row * 132 + c + 0] = v4.x;
        vs[row * 132 + c + 1] = v4.y;
        vs[row * 132 + c + 2] = v4.z;
        vs[row * 132 + c + 3] = v4.w;
    }
    if (tid < 225) bt[tid] = bias_table[tid];
    __syncthreads();

    const int r = tid >> 2;
    const int g = tid & 3;
    const int ry = r >> 3, rx = r & 7;

    unsigned long long acc[8];
#pragma unroll
    for (int j = 0; j < 8; j++) acc[j] = 0ull;
#pragma unroll 4
    for (int d = 0; d < 128; d++) {
        unsigned long long qsp = splat2(qs[r * 132 + d]);
#pragma unroll
        for (int j = 0; j < 8; j++)
            fma2(acc[j], qsp, *(const unsigned long long*)(&kt[d * 66 + 2 * g + 8 * j]));
    }

    float e[16];
    float mx = -1e30f;
#pragma unroll
    for (int j = 0; j < 8; j++) {
        float lo, hi; unpack2(acc[j], lo, hi);
        int bidx = (ry - j + 7) * 15 + (rx - 2 * g + 7);
        lo += bt[bidx];
        hi += bt[bidx - 1];
        e[2 * j]     = lo;
        e[2 * j + 1] = hi;
        mx = fmaxf(mx, fmaxf(lo, hi));
    }
    mx = fmaxf(mx, __shfl_xor_sync(0xffffffffu, mx, 1));
    mx = fmaxf(mx, __shfl_xor_sync(0xffffffffu, mx, 2));
    float s = 0.0f;
#pragma unroll
    for (int i = 0; i < 16; i++) { e[i] = __expf(e[i] - mx); s += e[i]; }
    s += __shfl_xor_sync(0xffffffffu, s, 1);
    s += __shfl_xor_sync(0xffffffffu, s, 2);
    float inv = 1.0f / s;
#pragma unroll
    for (int j = 0; j < 8; j++) {
        at[r * 65 + 2 * g + 8 * j]     = e[2 * j]     * inv;
        at[r * 65 + 2 * g + 8 * j + 1] = e[2 * j + 1] * inv;
    }
    __syncwarp();

    unsigned long long o2[16];
#pragma unroll
    for (int j = 0; j < 16; j++) o2[j] = 0ull;
    for (int m = 0; m < 64; m++) {
        unsigned long long a2 = splat2(at[r * 65 + m]);
#pragma unroll
        for (int jc = 0; jc < 8; jc++) {
            ulonglong2 vv = *(const ulonglong2*)(&vs[m * 132 + g * 4 + 16 * jc]);
            fma2(o2[2 * jc],     a2, vv.x);
            fma2(o2[2 * jc + 1], a2, vv.y);
        }
    }
    __nv_bfloat16* op = out + ((long)(wi * 64 + r)) * DIMC + head * 128;
#pragma unroll
    for (int jc = 0; jc < 8; jc++) {
        float4 f;
        unpack2(o2[2 * jc],     f.x, f.y);
        unpack2(o2[2 * jc + 1], f.z, f.w);
        uint2 pk;
        pk.x = pack_bf2(f.x, f.y);
        pk.y = pack_bf2(f.z, f.w);
        *(uint2*)(op + g * 4 + 16 * jc) = pk;
    }
}

// ---------------------------------------------------------------------------
extern "C" void kernel_launch(void* const* d_in, const int* in_sizes, int n_in,
                              void* d_out, int out_size)
{
    const float* x      = (const float*)d_in[0];
    const float* ln1_g  = (const float*)d_in[1];
    const float* ln1_b  = (const float*)d_in[2];
    const float* qkv_w  = (const float*)d_in[3];
    const float* qkv_b  = (const float*)d_in[4];
    const float* proj_w = (const float*)d_in[5];
    const float* proj_b = (const float*)d_in[6];
    const float* btab   = (const float*)d_in[7];
    const float* ln2_g  = (const float*)d_in[8];
    const float* ln2_b  = (const float*)d_in[9];
    const float* mlp_w1 = (const float*)d_in[10];
    const float* mlp_b1 = (const float*)d_in[11];
    const float* mlp_w2 = (const float*)d_in[12];
    const float* mlp_b2 = (const float*)d_in[13];
    float* outp = (float*)d_out;

    float* S = nullptr;
    cudaGetSymbolAddress((void**)&S, g_scratch);
    __nv_bfloat16* hw   = (__nv_bfloat16*)(S + OFF_HW);
    float*         qkv  = S + OFF_QKV;
    __nv_bfloat16* aout = (__nv_bfloat16*)(S + OFF_AOUT);
    float*         x2   = S + OFF_X2;
    __nv_bfloat16* h2n  = (__nv_bfloat16*)(S + OFF_H2N);
    __nv_bfloat16* m1   = (__nv_bfloat16*)(S + OFF_MLP1);
    __nv_bfloat16* wq   = (__nv_bfloat16*)(S + OFF_WQKV);
    __nv_bfloat16* wp   = (__nv_bfloat16*)(S + OFF_WPROJ);
    __nv_bfloat16* w1   = (__nv_bfloat16*)(S + OFF_WM1);
    __nv_bfloat16* w2   = (__nv_bfloat16*)(S + OFF_WM2);

    cudaFuncSetAttribute(attn_kernel, cudaFuncAttributeMaxDynamicSharedMemorySize,
                         ATTN_SMEM_BYTES);
    cudaFuncSetAttribute(mma_gemm, cudaFuncAttributeMaxDynamicSharedMemorySize,
                         GSMEM_BYTES);

    // transposed bf16 weights [N][K]
    transpose_kernel<<<dim3(48, 16), dim3(32, 8)>>>(qkv_w, wq, 512, 1536);
    transpose_kernel<<<dim3(16, 16), dim3(32, 8)>>>(proj_w, wp, 512, 512);
    transpose_kernel<<<dim3(64, 16), dim3(32, 8)>>>(mlp_w1, w1, 512, 2048);
    transpose_kernel<<<dim3(16, 64), dim3(32, 8)>>>(mlp_w2, w2, 2048, 512);

    // 1) LN1 + cyclic shift + window partition (bf16 out)
    ln_kernel<<<TOKENS, 128>>>(x, ln1_g, ln1_b, hw, 1);
    // 2) QKV GEMM (f32 out)
    mma_gemm<<<dim3(12, 256), 256, GSMEM_BYTES>>>(hw, wq, qkv_b, qkv,
                                                  512, 1536, 0, nullptr);
    // 3) windowed attention (bf16 out)
    attn_kernel<<<NWIN * 4, 256, ATTN_SMEM_BYTES>>>(qkv, btab, aout);
    // 4) proj + window reverse + unshift + residual(x) -> x2 (f32)
    mma_gemm<<<dim3(4, 256), 256, GSMEM_BYTES>>>(aout, wp, proj_b, x2,
                                                 512, 512, 1, x);
    // 5) LN2 (bf16 out)
    ln_kernel<<<TOKENS, 128>>>(x2, ln2_g, ln2_b, h2n, 0);
    // 6) MLP1 + exact GELU (bf16 out)
    mma_gemm<<<dim3(16, 256), 256, GSMEM_BYTES>>>(h2n, w1, mlp_b1, m1,
                                                  512, 2048, 2, nullptr);
    // 7) MLP2 + residual(x2) -> output (f32)
    mma_gemm<<<dim3(4, 256), 256, GSMEM_BYTES>>>(m1, w2, mlp_b2, outp,
                                                 2048, 512, 3, x2);
}